// round 14
// baseline (speedup 1.0000x reference)
#include <cuda_runtime.h>
#include <math.h>

#define N_NODES 10000
#define N_EDGES 160000
#define FEAT_DIM 320
#define AGG_DIM 768
#define ETILE 128

typedef unsigned long long u64;

__device__ float g_feat[N_NODES * FEAT_DIM];
__device__ float g_self[N_NODES * FEAT_DIM];
__device__ float g_agg [N_NODES * AGG_DIM];
// counting-sort scratch
__device__ int g_cnt [N_NODES];
__device__ int g_off [N_NODES];
__device__ int g_fill[N_NODES];
__device__ int g_perm[N_EDGES];

__device__ __forceinline__ float gelu_tanh(float x) {
    float x3 = x * x * x;
    float z  = 0.7978845608028654f * (x + 0.044715f * x3);
    float t;
    asm("tanh.approx.f32 %0, %1;" : "=f"(t) : "f"(z));
    return 0.5f * x * (1.0f + t);
}

__device__ __forceinline__ void red4(float* p, float4 v) {
    asm volatile("red.global.add.v4.f32 [%0], {%1,%2,%3,%4};"
                 :: "l"(p), "f"(v.x), "f"(v.y), "f"(v.z), "f"(v.w) : "memory");
}
__device__ __forceinline__ void red2(float* p, float a, float b) {
    asm volatile("red.global.add.v2.f32 [%0], {%1,%2};"
                 :: "l"(p), "f"(a), "f"(b) : "memory");
}

__device__ __forceinline__ u64 dupf(float x) {
    u64 r; asm("mov.b64 %0, {%1, %1};" : "=l"(r) : "f"(x)); return r;
}
__device__ __forceinline__ void unpack2(u64 v, float& lo, float& hi) {
    asm("mov.b64 {%0, %1}, %2;" : "=f"(lo), "=f"(hi) : "l"(v));
}
#define FFMA2(d, a, b, c) asm("fma.rn.f32x2 %0, %1, %2, %3;" : "=l"(d) : "l"(a), "l"(b), "l"(c))

// ---------------------------------------------------------------------------
// Counting sort of edges by dst
// ---------------------------------------------------------------------------
__global__ void hist_kernel(const int* __restrict__ edst) {
    int e = blockIdx.x * 256 + threadIdx.x;
    if (e < N_EDGES) atomicAdd(&g_cnt[edst[e]], 1);
}

__global__ void __launch_bounds__(1024) scan_kernel() {
    __shared__ int part[1024];
    const int t = threadIdx.x;
    const int base = t * 10;
    int local[10];
    int s = 0;
    #pragma unroll
    for (int j = 0; j < 10; ++j) {
        int idx = base + j;
        int c = (idx < N_NODES) ? g_cnt[idx] : 0;
        local[j] = s; s += c;
    }
    part[t] = s;
    __syncthreads();
    for (int off = 1; off < 1024; off <<= 1) {
        int v = (t >= off) ? part[t - off] : 0;
        __syncthreads();
        part[t] += v;
        __syncthreads();
    }
    int pre = (t == 0) ? 0 : part[t - 1];
    #pragma unroll
    for (int j = 0; j < 10; ++j) {
        int idx = base + j;
        if (idx < N_NODES) g_off[idx] = pre + local[j];
    }
}

__global__ void scatter_kernel(const int* __restrict__ edst) {
    int e = blockIdx.x * 256 + threadIdx.x;
    if (e < N_EDGES) {
        int d = edst[e];
        int pos = g_off[d] + atomicAdd(&g_fill[d], 1);
        g_perm[pos] = e;
    }
}

// ---------------------------------------------------------------------------
// Kernel A (R12-proven): 32 nodes/block, 256 threads. Weights staged in
// k-chunks of 64 (sW 32KB) -> total smem 76.3KB -> 3 CTAs/SM.
// ---------------------------------------------------------------------------
__global__ void __launch_bounds__(256) node_pre_kernel(
    const float* __restrict__ node,
    const float* __restrict__ Wa0, const float* __restrict__ Wa1,
    const float* __restrict__ Wb0, const float* __restrict__ Wb1)
{
    extern __shared__ float sm[];
    float* xT = sm;               // 320 x 34  (43520 B)
    float* sW = sm + 320 * 34;    // 64 x 128  (32768 B)
    const int tid = threadIdx.x;
    const int nb  = blockIdx.x * 32;

    for (int idx = tid; idx < 32 * 320; idx += 256) {
        int n = idx / 320, k = idx % 320;
        float v = (nb + n < N_NODES) ? node[(nb + n) * 320 + k] : 0.f;
        xT[k * 34 + n] = v;
    }

    const int n0s = (tid >> 5) * 4;
    const int u0s = (tid & 31) * 4;
    for (int w = 0; w < 2; ++w) {
        const float* W = w ? Wb0 : Wa0;
        float* dst     = w ? g_self : g_feat;
        u64 acc[2][4] = {};
        for (int kc = 0; kc < 2; ++kc) {
            __syncthreads();
            for (int idx = tid; idx < 2048; idx += 256)
                ((float4*)sW)[idx] = ((const float4*)W)[kc * 2048 + idx];
            __syncthreads();
            #pragma unroll 4
            for (int k = 0; k < 64; ++k) {
                int kk = kc * 64 + k;
                u64 a01 = *(const u64*)&xT[kk * 34 + n0s];
                u64 a23 = *(const u64*)&xT[kk * 34 + n0s + 2];
                float4 b = *(const float4*)&sW[k * 128 + u0s];
                u64 b0 = dupf(b.x), b1 = dupf(b.y), b2 = dupf(b.z), b3 = dupf(b.w);
                FFMA2(acc[0][0], a01, b0, acc[0][0]); FFMA2(acc[0][1], a01, b1, acc[0][1]);
                FFMA2(acc[0][2], a01, b2, acc[0][2]); FFMA2(acc[0][3], a01, b3, acc[0][3]);
                FFMA2(acc[1][0], a23, b0, acc[1][0]); FFMA2(acc[1][1], a23, b1, acc[1][1]);
                FFMA2(acc[1][2], a23, b2, acc[1][2]); FFMA2(acc[1][3], a23, b3, acc[1][3]);
            }
        }
        const float sc = 0.08838834764831845f;
        #pragma unroll
        for (int p = 0; p < 2; ++p) {
            float lo[4], hi[4];
            #pragma unroll
            for (int j = 0; j < 4; ++j) unpack2(acc[p][j], lo[j], hi[j]);
            int na = nb + n0s + 2 * p, nc = na + 1;
            if (na < N_NODES)
                *(float4*)&dst[na * 320 + u0s] = make_float4(lo[0]*sc, lo[1]*sc, lo[2]*sc, lo[3]*sc);
            if (nc < N_NODES)
                *(float4*)&dst[nc * 320 + u0s] = make_float4(hi[0]*sc, hi[1]*sc, hi[2]*sc, hi[3]*sc);
        }
    }

    // ---- vector part: Wa1 (half 0) and Wb1 (half 1) concurrently ----
    __syncthreads();
    for (int idx = tid; idx < 1024; idx += 256) ((float4*)sW)[idx] = ((const float4*)Wa1)[idx];
    for (int idx = tid; idx < 1024; idx += 256) ((float4*)(sW + 4096))[idx] = ((const float4*)Wb1)[idx];
    __syncthreads();
    {
        const int half = tid >> 7;
        const int wt   = tid & 127;
        const int n0   = (wt >> 4) * 4;
        const int u0   = (wt & 15) * 4;
        const float* sWh = sW + half * 4096;
        float* dst       = half ? g_self : g_feat;
        for (int i = 0; i < 3; ++i) {
            u64 acc[2][4] = {};
            #pragma unroll 4
            for (int v = 0; v < 64; ++v) {
                int k = 128 + v * 3 + i;
                u64 a01 = *(const u64*)&xT[k * 34 + n0];
                u64 a23 = *(const u64*)&xT[k * 34 + n0 + 2];
                float4 b = *(const float4*)&sWh[v * 64 + u0];
                u64 b0 = dupf(b.x), b1 = dupf(b.y), b2 = dupf(b.z), b3 = dupf(b.w);
                FFMA2(acc[0][0], a01, b0, acc[0][0]); FFMA2(acc[0][1], a01, b1, acc[0][1]);
                FFMA2(acc[0][2], a01, b2, acc[0][2]); FFMA2(acc[0][3], a01, b3, acc[0][3]);
                FFMA2(acc[1][0], a23, b0, acc[1][0]); FFMA2(acc[1][1], a23, b1, acc[1][1]);
                FFMA2(acc[1][2], a23, b2, acc[1][2]); FFMA2(acc[1][3], a23, b3, acc[1][3]);
            }
            const float sc = 0.125f;
            #pragma unroll
            for (int p = 0; p < 2; ++p) {
                float lo[4], hi[4];
                #pragma unroll
                for (int j = 0; j < 4; ++j) unpack2(acc[p][j], lo[j], hi[j]);
                int na = nb + n0 + 2 * p, nc = na + 1;
                #pragma unroll
                for (int j = 0; j < 4; ++j) {
                    if (na < N_NODES) dst[na * 320 + 128 + (u0 + j) * 3 + i] = lo[j] * sc;
                    if (nc < N_NODES) dst[nc * 320 + 128 + (u0 + j) * 3 + i] = hi[j] * sc;
                }
            }
        }
    }
}

// ---------------------------------------------------------------------------
// Kernel B (v14): 128-edge tiles, 512 threads (16 warps). Same per-warp
// mappings as the R8-proven version; stage strides 64 -> 128.
// ---------------------------------------------------------------------------
__global__ void __launch_bounds__(512) edge_kernel(
    const float* __restrict__ edge_attr, const float* __restrict__ esa,
    const float* __restrict__ M1, const float* __restrict__ M2,
    const float* __restrict__ Wtp0, const float* __restrict__ Wtp1,
    const float* __restrict__ Wtp2, const float* __restrict__ Wtp3,
    const int* __restrict__ esrc, const int* __restrict__ edst)
{
    extern __shared__ float sm[];
    float* sInT = sm;             // 8 x 128
    float* sH1T = sm + 1024;      // 64 x 128  [chan][edge]
    float* sH2T = sH1T + 8192;    // 64 x 128  [chan][edge]
    int*   sSrc = (int*)(sH2T + 8192);   // 128
    int*   sDst = sSrc + 128;            // 128
    float* sY   = (float*)(sDst + 128);  // 128 x 4

    const int tid = threadIdx.x;
    const int eb  = blockIdx.x * ETILE;

    for (int idx = tid; idx < ETILE * 8; idx += 512) {
        int el = idx >> 3, k = idx & 7;
        int e = __ldg(&g_perm[eb + el]);
        sInT[k * 128 + el] = esa[e * 8 + k];
    }
    if (tid < 128) {
        int e = __ldg(&g_perm[eb + tid]);
        sSrc[tid] = esrc[e];
        sDst[tid] = edst[e];
        float4 y = *(const float4*)&edge_attr[e * 4];
        sY[tid * 4 + 0] = y.x; sY[tid * 4 + 1] = y.y;
        sY[tid * 4 + 2] = y.z; sY[tid * 4 + 3] = y.w;
    }
    __syncthreads();

    // h1 = gelu((esa @ M1)/sqrt(8))
    for (int idx = tid; idx < 8192; idx += 512) {
        int u = idx >> 7, el = idx & 127;
        float s = 0.f;
        #pragma unroll
        for (int k = 0; k < 8; ++k) s += sInT[k * 128 + el] * __ldg(&M1[k * 64 + u]);
        sH1T[idx] = gelu_tanh(s * 0.3535533905932738f);
    }
    __syncthreads();

    // h2 = gelu((h1 @ M2)/sqrt(64)), M2 straight from gmem
    {
        const int e0 = (tid & 31) * 4, u0 = (tid >> 5) * 4;
        u64 acc[4][2] = {};
        #pragma unroll 4
        for (int k = 0; k < 64; ++k) {
            float4 a = *(const float4*)&sH1T[k * 128 + e0];
            u64 ad0 = dupf(a.x), ad1 = dupf(a.y), ad2 = dupf(a.z), ad3 = dupf(a.w);
            ulonglong2 b = __ldg((const ulonglong2*)&M2[k * 64 + u0]);
            FFMA2(acc[0][0], ad0, b.x, acc[0][0]); FFMA2(acc[0][1], ad0, b.y, acc[0][1]);
            FFMA2(acc[1][0], ad1, b.x, acc[1][0]); FFMA2(acc[1][1], ad1, b.y, acc[1][1]);
            FFMA2(acc[2][0], ad2, b.x, acc[2][0]); FFMA2(acc[2][1], ad2, b.y, acc[2][1]);
            FFMA2(acc[3][0], ad3, b.x, acc[3][0]); FFMA2(acc[3][1], ad3, b.y, acc[3][1]);
        }
        #pragma unroll
        for (int e = 0; e < 4; ++e)
            #pragma unroll
            for (int j = 0; j < 2; ++j) {
                float lo, hi; unpack2(acc[e][j], lo, hi);
                sH2T[(u0 + 2*j    ) * 128 + e0 + e] = gelu_tanh(lo * 0.125f);
                sH2T[(u0 + 2*j + 1) * 128 + e0 + e] = gelu_tanh(hi * 0.125f);
            }
    }
    __syncthreads();

    // ============ barrier-free fused phases ============
    const int wid = tid >> 5, lane = tid & 31;
    const int we0 = wid * 8;

    // ---- p0: w0 -> mid0a (run-accumulated) ----
    {
        u64 acc[4][4] = {};
        #pragma unroll 4
        for (int k = 0; k < 64; ++k) {
            const float* ap = &sH2T[k * 128 + we0];
            ulonglong2 aa0 = *(const ulonglong2*)(ap);
            ulonglong2 aa1 = *(const ulonglong2*)(ap + 4);
            u64 a0 = aa0.x, a1 = aa0.y, a2 = aa1.x, a3 = aa1.y;
            float4 b = __ldg((const float4*)&Wtp0[k * 128 + lane * 4]);
            u64 b0 = dupf(b.x), b1 = dupf(b.y), b2 = dupf(b.z), b3 = dupf(b.w);
            FFMA2(acc[0][0], a0, b0, acc[0][0]); FFMA2(acc[0][1], a0, b1, acc[0][1]);
            FFMA2(acc[0][2], a0, b2, acc[0][2]); FFMA2(acc[0][3], a0, b3, acc[0][3]);
            FFMA2(acc[1][0], a1, b0, acc[1][0]); FFMA2(acc[1][1], a1, b1, acc[1][1]);
            FFMA2(acc[1][2], a1, b2, acc[1][2]); FFMA2(acc[1][3], a1, b3, acc[1][3]);
            FFMA2(acc[2][0], a2, b0, acc[2][0]); FFMA2(acc[2][1], a2, b1, acc[2][1]);
            FFMA2(acc[2][2], a2, b2, acc[2][2]); FFMA2(acc[2][3], a2, b3, acc[2][3]);
            FFMA2(acc[3][0], a3, b0, acc[3][0]); FFMA2(acc[3][1], a3, b1, acc[3][1]);
            FFMA2(acc[3][2], a3, b2, acc[3][2]); FFMA2(acc[3][3], a3, b3, acc[3][3]);
        }
        int cur = sDst[we0];
        float4 av = make_float4(0.f, 0.f, 0.f, 0.f);
        #pragma unroll
        for (int p = 0; p < 4; ++p) {
            float lo[4], hi[4];
            #pragma unroll
            for (int j = 0; j < 4; ++j) unpack2(acc[p][j], lo[j], hi[j]);
            #pragma unroll
            for (int h = 0; h < 2; ++h) {
                int e = we0 + 2 * p + h;
                int dst = sDst[e];
                if (dst != cur) {
                    red4(&g_agg[cur * 768 + lane * 4], av);
                    av = make_float4(0.f, 0.f, 0.f, 0.f);
                    cur = dst;
                }
                float y0 = sY[e * 4] * 0.125f;
                float4 f = *(const float4*)&g_feat[sSrc[e] * 320 + lane * 4];
                float wa = h ? hi[0] : lo[0], wb = h ? hi[1] : lo[1];
                float wc = h ? hi[2] : lo[2], wd = h ? hi[3] : lo[3];
                av.x += wa*f.x*y0; av.y += wb*f.y*y0;
                av.z += wc*f.z*y0; av.w += wd*f.w*y0;
            }
        }
        red4(&g_agg[cur * 768 + lane * 4], av);
    }

    // ---- p1: w1 -> mid1a (run-accumulated) ----
    {
        u64 acc[4][4] = {};
        #pragma unroll 4
        for (int k = 0; k < 64; ++k) {
            const float* ap = &sH2T[k * 128 + we0];
            ulonglong2 aa0 = *(const ulonglong2*)(ap);
            ulonglong2 aa1 = *(const ulonglong2*)(ap + 4);
            u64 a0 = aa0.x, a1 = aa0.y, a2 = aa1.x, a3 = aa1.y;
            float4 b = __ldg((const float4*)&Wtp1[k * 128 + lane * 4]);
            u64 b0 = dupf(b.x), b1 = dupf(b.y), b2 = dupf(b.z), b3 = dupf(b.w);
            FFMA2(acc[0][0], a0, b0, acc[0][0]); FFMA2(acc[0][1], a0, b1, acc[0][1]);
            FFMA2(acc[0][2], a0, b2, acc[0][2]); FFMA2(acc[0][3], a0, b3, acc[0][3]);
            FFMA2(acc[1][0], a1, b0, acc[1][0]); FFMA2(acc[1][1], a1, b1, acc[1][1]);
            FFMA2(acc[1][2], a1, b2, acc[1][2]); FFMA2(acc[1][3], a1, b3, acc[1][3]);
            FFMA2(acc[2][0], a2, b0, acc[2][0]); FFMA2(acc[2][1], a2, b1, acc[2][1]);
            FFMA2(acc[2][2], a2, b2, acc[2][2]); FFMA2(acc[2][3], a2, b3, acc[2][3]);
            FFMA2(acc[3][0], a3, b0, acc[3][0]); FFMA2(acc[3][1], a3, b1, acc[3][1]);
            FFMA2(acc[3][2], a3, b2, acc[3][2]); FFMA2(acc[3][3], a3, b3, acc[3][3]);
        }
        int cur = sDst[we0];
        float a[12];
        #pragma unroll
        for (int j = 0; j < 12; ++j) a[j] = 0.f;
        #pragma unroll
        for (int p = 0; p < 4; ++p) {
            float lo[4], hi[4];
            #pragma unroll
            for (int j = 0; j < 4; ++j) unpack2(acc[p][j], lo[j], hi[j]);
            #pragma unroll
            for (int h = 0; h < 2; ++h) {
                int e = we0 + 2 * p + h;
                int dst = sDst[e];
                if (dst != cur) {
                    float* bp = &g_agg[cur * 768 + 192 + lane * 12];
                    red4(bp,     make_float4(a[0], a[1], a[2],  a[3]));
                    red4(bp + 4, make_float4(a[4], a[5], a[6],  a[7]));
                    red4(bp + 8, make_float4(a[8], a[9], a[10], a[11]));
                    #pragma unroll
                    for (int j = 0; j < 12; ++j) a[j] = 0.f;
                    cur = dst;
                }
                float ya = sY[e*4+1] * 0.125f, yb = sY[e*4+2] * 0.125f, yc = sY[e*4+3] * 0.125f;
                float4 f = *(const float4*)&g_feat[sSrc[e] * 320 + lane * 4];
                float wa = h ? hi[0] : lo[0], wb = h ? hi[1] : lo[1];
                float wc = h ? hi[2] : lo[2], wd = h ? hi[3] : lo[3];
                float t0 = wa*f.x, t1 = wb*f.y, t2 = wc*f.z, t3 = wd*f.w;
                a[0] += t0*ya; a[1]  += t0*yb; a[2]  += t0*yc;
                a[3] += t1*ya; a[4]  += t1*yb; a[5]  += t1*yc;
                a[6] += t2*ya; a[7]  += t2*yb; a[8]  += t2*yc;
                a[9] += t3*ya; a[10] += t3*yb; a[11] += t3*yc;
            }
        }
        float* bp = &g_agg[cur * 768 + 192 + lane * 12];
        red4(bp,     make_float4(a[0], a[1], a[2],  a[3]));
        red4(bp + 4, make_float4(a[4], a[5], a[6],  a[7]));
        red4(bp + 8, make_float4(a[8], a[9], a[10], a[11]));
    }

    // ---- p2+p3: w2 -> mid1b, w3 -> mid0b (run-accumulated) ----
    {
        u64 ac2[4][2] = {}, ac3[4][2] = {};
        #pragma unroll 4
        for (int k = 0; k < 64; ++k) {
            const float* ap = &sH2T[k * 128 + we0];
            ulonglong2 aa0 = *(const ulonglong2*)(ap);
            ulonglong2 aa1 = *(const ulonglong2*)(ap + 4);
            u64 a0 = aa0.x, a1 = aa0.y, a2 = aa1.x, a3 = aa1.y;
            float2 b2v = __ldg((const float2*)&Wtp2[k * 64 + lane * 2]);
            float2 b3v = __ldg((const float2*)&Wtp3[k * 64 + lane * 2]);
            u64 b20 = dupf(b2v.x), b21 = dupf(b2v.y);
            u64 b30 = dupf(b3v.x), b31 = dupf(b3v.y);
            FFMA2(ac2[0][0], a0, b20, ac2[0][0]); FFMA2(ac2[0][1], a0, b21, ac2[0][1]);
            FFMA2(ac2[1][0], a1, b20, ac2[1][0]); FFMA2(ac2[1][1], a1, b21, ac2[1][1]);
            FFMA2(ac2[2][0], a2, b20, ac2[2][0]); FFMA2(ac2[2][1], a2, b21, ac2[2][1]);
            FFMA2(ac2[3][0], a3, b20, ac2[3][0]); FFMA2(ac2[3][1], a3, b21, ac2[3][1]);
            FFMA2(ac3[0][0], a0, b30, ac3[0][0]); FFMA2(ac3[0][1], a0, b31, ac3[0][1]);
            FFMA2(ac3[1][0], a1, b30, ac3[1][0]); FFMA2(ac3[1][1], a1, b31, ac3[1][1]);
            FFMA2(ac3[2][0], a2, b30, ac3[2][0]); FFMA2(ac3[2][1], a2, b31, ac3[2][1]);
            FFMA2(ac3[3][0], a3, b30, ac3[3][0]); FFMA2(ac3[3][1], a3, b31, ac3[3][1]);
        }
        const float k3 = 0.125f * 0.5773502691896258f;
        int cur = sDst[we0];
        float q2[6] = {0.f, 0.f, 0.f, 0.f, 0.f, 0.f};
        float q3[2] = {0.f, 0.f};
        #pragma unroll
        for (int p = 0; p < 4; ++p) {
            float lo20, hi20, lo21, hi21, lo30, hi30, lo31, hi31;
            unpack2(ac2[p][0], lo20, hi20); unpack2(ac2[p][1], lo21, hi21);
            unpack2(ac3[p][0], lo30, hi30); unpack2(ac3[p][1], lo31, hi31);
            #pragma unroll
            for (int h = 0; h < 2; ++h) {
                int e = we0 + 2 * p + h;
                int dst = sDst[e];
                if (dst != cur) {
                    float* bp = &g_agg[cur * 768 + 576 + lane * 6];
                    red2(bp,     q2[0], q2[1]);
                    red2(bp + 2, q2[2], q2[3]);
                    red2(bp + 4, q2[4], q2[5]);
                    red2(&g_agg[cur * 768 + 128 + lane * 2], q3[0] * k3, q3[1] * k3);
                    #pragma unroll
                    for (int j = 0; j < 6; ++j) q2[j] = 0.f;
                    q3[0] = 0.f; q3[1] = 0.f;
                    cur = dst;
                }
                float y0 = sY[e*4] * 0.125f;
                float ya = sY[e*4+1], yb = sY[e*4+2], yc = sY[e*4+3];
                const float* fb = &g_feat[sSrc[e] * 320 + 128 + lane * 6];
                float2 f0 = *(const float2*)fb;
                float2 f1 = *(const float2*)(fb + 2);
                float2 f2 = *(const float2*)(fb + 4);
                float w2x = h ? hi20 : lo20, w2y = h ? hi21 : lo21;
                float w3x = h ? hi30 : lo30, w3y = h ? hi31 : lo31;
                q2[0] += w2x*f0.x*y0; q2[1] += w2x*f0.y*y0; q2[2] += w2x*f1.x*y0;
                q2[3] += w2y*f1.y*y0; q2[4] += w2y*f2.x*y0; q2[5] += w2y*f2.y*y0;
                float d0 = f0.x*ya + f0.y*yb + f1.x*yc;
                float d1 = f1.y*ya + f2.x*yb + f2.y*yc;
                q3[0] += w3x*d0; q3[1] += w3y*d1;
            }
        }
        float* bp = &g_agg[cur * 768 + 576 + lane * 6];
        red2(bp,     q2[0], q2[1]);
        red2(bp + 2, q2[2], q2[3]);
        red2(bp + 4, q2[4], q2[5]);
        red2(&g_agg[cur * 768 + 128 + lane * 2], q3[0] * k3, q3[1] * k3);
    }
}

// ---------------------------------------------------------------------------
// Kernel D (R12-proven, full weight stage): output transforms.
// ---------------------------------------------------------------------------
__global__ void __launch_bounds__(256) node_out_kernel(
    const float* __restrict__ Wo0, const float* __restrict__ Wo1,
    float* __restrict__ out)
{
    extern __shared__ float sm[];
    float* zT = sm;              // 192 x 34
    float* sW = sm + 192 * 34;   // 192 x 64
    const int tid = threadIdx.x;
    const int nb  = blockIdx.x * 32;
    const int n0 = (tid >> 5) * 4;
    const int u0 = (tid & 31) * 2;
    const float cs    = 0.9238795325112867f;
    const float kconv = 0.38268343236508984f * 0.25f * 0.07216878364870323f;

    for (int idx = tid; idx < 32 * 192; idx += 256) {
        int n = idx / 192, k = idx % 192;
        zT[k * 34 + n] = (nb + n < N_NODES) ? g_agg[(nb + n) * 768 + k] : 0.f;
    }
    for (int uc = 0; uc < 128; uc += 64) {
        __syncthreads();
        for (int idx = tid; idx < 192 * 64; idx += 256) {
            int k = idx >> 6, u = idx & 63;
            sW[idx] = Wo0[k * 128 + uc + u];
        }
        __syncthreads();
        u64 acc[2][2] = {};
        #pragma unroll 4
        for (int k = 0; k < 192; ++k) {
            u64 a01 = *(const u64*)&zT[k * 34 + n0];
            u64 a23 = *(const u64*)&zT[k * 34 + n0 + 2];
            float2 b = *(const float2*)&sW[k * 64 + u0];
            u64 b0 = dupf(b.x), b1 = dupf(b.y);
            FFMA2(acc[0][0], a01, b0, acc[0][0]); FFMA2(acc[0][1], a01, b1, acc[0][1]);
            FFMA2(acc[1][0], a23, b0, acc[1][0]); FFMA2(acc[1][1], a23, b1, acc[1][1]);
        }
        #pragma unroll
        for (int p = 0; p < 2; ++p) {
            float lo[2], hi[2];
            unpack2(acc[p][0], lo[0], hi[0]);
            unpack2(acc[p][1], lo[1], hi[1]);
            int na = nb + n0 + 2 * p, nc = na + 1;
            if (na < N_NODES) {
                const float* sf = &g_self[na * 320 + uc + u0];
                *(float2*)&out[na * 320 + uc + u0] =
                    make_float2(cs*sf[0] + kconv*lo[0], cs*sf[1] + kconv*lo[1]);
            }
            if (nc < N_NODES) {
                const float* sf = &g_self[nc * 320 + uc + u0];
                *(float2*)&out[nc * 320 + uc + u0] =
                    make_float2(cs*sf[0] + kconv*hi[0], cs*sf[1] + kconv*hi[1]);
            }
        }
    }

    __syncthreads();
    for (int idx = tid; idx < 192 * 64; idx += 256) sW[idx] = Wo1[idx];
    for (int i = 0; i < 3; ++i) {
        __syncthreads();
        for (int idx = tid; idx < 32 * 192; idx += 256) {
            int n = idx / 192, k = idx % 192;
            zT[k * 34 + n] = (nb + n < N_NODES) ? g_agg[(nb + n) * 768 + 192 + k * 3 + i] : 0.f;
        }
        __syncthreads();
        u64 acc[2][2] = {};
        #pragma unroll 4
        for (int k = 0; k < 192; ++k) {
            u64 a01 = *(const u64*)&zT[k * 34 + n0];
            u64 a23 = *(const u64*)&zT[k * 34 + n0 + 2];
            float2 b = *(const float2*)&sW[k * 64 + u0];
            u64 b0 = dupf(b.x), b1 = dupf(b.y);
            FFMA2(acc[0][0], a01, b0, acc[0][0]); FFMA2(acc[0][1], a01, b1, acc[0][1]);
            FFMA2(acc[1][0], a23, b0, acc[1][0]); FFMA2(acc[1][1], a23, b1, acc[1][1]);
        }
        #pragma unroll
        for (int p = 0; p < 2; ++p) {
            float lo[2], hi[2];
            unpack2(acc[p][0], lo[0], hi[0]);
            unpack2(acc[p][1], lo[1], hi[1]);
            int na = nb + n0 + 2 * p, nc = na + 1;
            #pragma unroll
            for (int j = 0; j < 2; ++j) {
                if (na < N_NODES)
                    out[na * 320 + 128 + (u0 + j) * 3 + i] =
                        cs * g_self[na * 320 + 128 + (u0 + j) * 3 + i] + kconv * lo[j];
                if (nc < N_NODES)
                    out[nc * 320 + 128 + (u0 + j) * 3 + i] =
                        cs * g_self[nc * 320 + 128 + (u0 + j) * 3 + i] + kconv * hi[j];
            }
        }
    }
}

// ---------------------------------------------------------------------------
extern "C" void kernel_launch(void* const* d_in, const int* in_sizes, int n_in,
                              void* d_out, int out_size)
{
    const float* node = (const float*)d_in[0];
    const float* edge_attr = (const float*)d_in[1];
    const float* esa  = (const float*)d_in[2];
    const float* Wa0  = (const float*)d_in[3];
    const float* Wa1  = (const float*)d_in[4];
    const float* Wb0  = (const float*)d_in[5];
    const float* Wb1  = (const float*)d_in[6];
    const float* M1   = (const float*)d_in[7];
    const float* M2   = (const float*)d_in[8];
    const float* Wtp0 = (const float*)d_in[9];
    const float* Wtp1 = (const float*)d_in[10];
    const float* Wtp2 = (const float*)d_in[11];
    const float* Wtp3 = (const float*)d_in[12];
    const float* Wo0  = (const float*)d_in[13];
    const float* Wo1  = (const float*)d_in[14];
    const int* esrc   = (const int*)d_in[15];
    const int* edst   = (const int*)d_in[16];
    float* out = (float*)d_out;

    const int smemA = (320 * 34 + 64 * 128) * 4;                            // 76288
    const int smemB = (1024 + 8192 + 8192) * 4 + 128 * 4 * 2 + 128 * 4 * 4; // 72704
    const int smemD = (192 * 34 + 192 * 64) * 4;                            // 75264

    cudaFuncSetAttribute(node_pre_kernel, cudaFuncAttributeMaxDynamicSharedMemorySize, smemA);
    cudaFuncSetAttribute(edge_kernel,     cudaFuncAttributeMaxDynamicSharedMemorySize, smemB);
    cudaFuncSetAttribute(node_out_kernel, cudaFuncAttributeMaxDynamicSharedMemorySize, smemD);

    void *aggp = nullptr, *cntp = nullptr, *fillp = nullptr;
    cudaGetSymbolAddress(&aggp,  g_agg);
    cudaGetSymbolAddress(&cntp,  g_cnt);
    cudaGetSymbolAddress(&fillp, g_fill);
    cudaMemsetAsync(aggp,  0, sizeof(float) * (size_t)N_NODES * AGG_DIM);
    cudaMemsetAsync(cntp,  0, sizeof(int) * N_NODES);
    cudaMemsetAsync(fillp, 0, sizeof(int) * N_NODES);

    hist_kernel<<<(N_EDGES + 255) / 256, 256>>>(edst);
    scan_kernel<<<1, 1024>>>();
    scatter_kernel<<<(N_EDGES + 255) / 256, 256>>>(edst);

    node_pre_kernel<<<(N_NODES + 31) / 32, 256, smemA>>>(node, Wa0, Wa1, Wb0, Wb1);
    edge_kernel<<<N_EDGES / ETILE, 512, smemB>>>(edge_attr, esa, M1, M2,
                                                 Wtp0, Wtp1, Wtp2, Wtp3, esrc, edst);
    node_out_kernel<<<(N_NODES + 31) / 32, 256, smemD>>>(Wo0, Wo1, out);
}

// round 15
// speedup vs baseline: 1.1697x; 1.1697x over previous
#include <cuda_runtime.h>
#include <math.h>

#define N_NODES 10000
#define N_EDGES 160000
#define FEAT_DIM 320
#define AGG_DIM 768

typedef unsigned long long u64;

__device__ float g_feat[N_NODES * FEAT_DIM];
__device__ float g_self[N_NODES * FEAT_DIM];
__device__ float g_agg [N_NODES * AGG_DIM];
// counting-sort scratch
__device__ int g_cnt [N_NODES];
__device__ int g_off [N_NODES];   // exclusive prefix; consumed (destructively) by scatter
__device__ int g_perm[N_EDGES];

__device__ __forceinline__ float gelu_tanh(float x) {
    float x3 = x * x * x;
    float z  = 0.7978845608028654f * (x + 0.044715f * x3);
    float t;
    asm("tanh.approx.f32 %0, %1;" : "=f"(t) : "f"(z));
    return 0.5f * x * (1.0f + t);
}

__device__ __forceinline__ void red4(float* p, float4 v) {
    asm volatile("red.global.add.v4.f32 [%0], {%1,%2,%3,%4};"
                 :: "l"(p), "f"(v.x), "f"(v.y), "f"(v.z), "f"(v.w) : "memory");
}
__device__ __forceinline__ void red2(float* p, float a, float b) {
    asm volatile("red.global.add.v2.f32 [%0], {%1,%2};"
                 :: "l"(p), "f"(a), "f"(b) : "memory");
}

__device__ __forceinline__ u64 dupf(float x) {
    u64 r; asm("mov.b64 %0, {%1, %1};" : "=l"(r) : "f"(x)); return r;
}
__device__ __forceinline__ void unpack2(u64 v, float& lo, float& hi) {
    asm("mov.b64 {%0, %1}, %2;" : "=f"(lo), "=f"(hi) : "l"(v));
}
#define FFMA2(d, a, b, c) asm("fma.rn.f32x2 %0, %1, %2, %3;" : "=l"(d) : "l"(a), "l"(b), "l"(c))

// ---------------------------------------------------------------------------
// Counting sort of edges by dst (g_off doubles as the fill cursor)
// ---------------------------------------------------------------------------
__global__ void hist_kernel(const int* __restrict__ edst) {
    int e = blockIdx.x * 256 + threadIdx.x;
    if (e < N_EDGES) atomicAdd(&g_cnt[edst[e]], 1);
}

__global__ void __launch_bounds__(1024) scan_kernel() {
    __shared__ int part[1024];
    const int t = threadIdx.x;
    const int base = t * 10;
    int local[10];
    int s = 0;
    #pragma unroll
    for (int j = 0; j < 10; ++j) {
        int idx = base + j;
        int c = (idx < N_NODES) ? g_cnt[idx] : 0;
        local[j] = s; s += c;
    }
    part[t] = s;
    __syncthreads();
    for (int off = 1; off < 1024; off <<= 1) {
        int v = (t >= off) ? part[t - off] : 0;
        __syncthreads();
        part[t] += v;
        __syncthreads();
    }
    int pre = (t == 0) ? 0 : part[t - 1];
    #pragma unroll
    for (int j = 0; j < 10; ++j) {
        int idx = base + j;
        if (idx < N_NODES) g_off[idx] = pre + local[j];
    }
}

__global__ void scatter_kernel(const int* __restrict__ edst) {
    int e = blockIdx.x * 256 + threadIdx.x;
    if (e < N_EDGES) {
        int pos = atomicAdd(&g_off[edst[e]], 1);   // destructive: g_off is the cursor
        g_perm[pos] = e;
    }
}

// ---------------------------------------------------------------------------
// Kernel A (R12-proven): 32 nodes/block, 256 threads. Weights staged in
// k-chunks of 64 (sW 32KB) -> total smem 76.3KB -> 3 CTAs/SM.
// ---------------------------------------------------------------------------
__global__ void __launch_bounds__(256) node_pre_kernel(
    const float* __restrict__ node,
    const float* __restrict__ Wa0, const float* __restrict__ Wa1,
    const float* __restrict__ Wb0, const float* __restrict__ Wb1)
{
    extern __shared__ float sm[];
    float* xT = sm;               // 320 x 34  (43520 B)
    float* sW = sm + 320 * 34;    // 64 x 128  (32768 B)
    const int tid = threadIdx.x;
    const int nb  = blockIdx.x * 32;

    for (int idx = tid; idx < 32 * 320; idx += 256) {
        int n = idx / 320, k = idx % 320;
        float v = (nb + n < N_NODES) ? node[(nb + n) * 320 + k] : 0.f;
        xT[k * 34 + n] = v;
    }

    const int n0s = (tid >> 5) * 4;
    const int u0s = (tid & 31) * 4;
    for (int w = 0; w < 2; ++w) {
        const float* W = w ? Wb0 : Wa0;
        float* dst     = w ? g_self : g_feat;
        u64 acc[2][4] = {};
        for (int kc = 0; kc < 2; ++kc) {
            __syncthreads();
            for (int idx = tid; idx < 2048; idx += 256)
                ((float4*)sW)[idx] = ((const float4*)W)[kc * 2048 + idx];
            __syncthreads();
            #pragma unroll 4
            for (int k = 0; k < 64; ++k) {
                int kk = kc * 64 + k;
                u64 a01 = *(const u64*)&xT[kk * 34 + n0s];
                u64 a23 = *(const u64*)&xT[kk * 34 + n0s + 2];
                float4 b = *(const float4*)&sW[k * 128 + u0s];
                u64 b0 = dupf(b.x), b1 = dupf(b.y), b2 = dupf(b.z), b3 = dupf(b.w);
                FFMA2(acc[0][0], a01, b0, acc[0][0]); FFMA2(acc[0][1], a01, b1, acc[0][1]);
                FFMA2(acc[0][2], a01, b2, acc[0][2]); FFMA2(acc[0][3], a01, b3, acc[0][3]);
                FFMA2(acc[1][0], a23, b0, acc[1][0]); FFMA2(acc[1][1], a23, b1, acc[1][1]);
                FFMA2(acc[1][2], a23, b2, acc[1][2]); FFMA2(acc[1][3], a23, b3, acc[1][3]);
            }
        }
        const float sc = 0.08838834764831845f;
        #pragma unroll
        for (int p = 0; p < 2; ++p) {
            float lo[4], hi[4];
            #pragma unroll
            for (int j = 0; j < 4; ++j) unpack2(acc[p][j], lo[j], hi[j]);
            int na = nb + n0s + 2 * p, nc = na + 1;
            if (na < N_NODES)
                *(float4*)&dst[na * 320 + u0s] = make_float4(lo[0]*sc, lo[1]*sc, lo[2]*sc, lo[3]*sc);
            if (nc < N_NODES)
                *(float4*)&dst[nc * 320 + u0s] = make_float4(hi[0]*sc, hi[1]*sc, hi[2]*sc, hi[3]*sc);
        }
    }

    // ---- vector part: Wa1 (half 0) and Wb1 (half 1) concurrently ----
    __syncthreads();
    for (int idx = tid; idx < 1024; idx += 256) ((float4*)sW)[idx] = ((const float4*)Wa1)[idx];
    for (int idx = tid; idx < 1024; idx += 256) ((float4*)(sW + 4096))[idx] = ((const float4*)Wb1)[idx];
    __syncthreads();
    {
        const int half = tid >> 7;
        const int wt   = tid & 127;
        const int n0   = (wt >> 4) * 4;
        const int u0   = (wt & 15) * 4;
        const float* sWh = sW + half * 4096;
        float* dst       = half ? g_self : g_feat;
        for (int i = 0; i < 3; ++i) {
            u64 acc[2][4] = {};
            #pragma unroll 4
            for (int v = 0; v < 64; ++v) {
                int k = 128 + v * 3 + i;
                u64 a01 = *(const u64*)&xT[k * 34 + n0];
                u64 a23 = *(const u64*)&xT[k * 34 + n0 + 2];
                float4 b = *(const float4*)&sWh[v * 64 + u0];
                u64 b0 = dupf(b.x), b1 = dupf(b.y), b2 = dupf(b.z), b3 = dupf(b.w);
                FFMA2(acc[0][0], a01, b0, acc[0][0]); FFMA2(acc[0][1], a01, b1, acc[0][1]);
                FFMA2(acc[0][2], a01, b2, acc[0][2]); FFMA2(acc[0][3], a01, b3, acc[0][3]);
                FFMA2(acc[1][0], a23, b0, acc[1][0]); FFMA2(acc[1][1], a23, b1, acc[1][1]);
                FFMA2(acc[1][2], a23, b2, acc[1][2]); FFMA2(acc[1][3], a23, b3, acc[1][3]);
            }
            const float sc = 0.125f;
            #pragma unroll
            for (int p = 0; p < 2; ++p) {
                float lo[4], hi[4];
                #pragma unroll
                for (int j = 0; j < 4; ++j) unpack2(acc[p][j], lo[j], hi[j]);
                int na = nb + n0 + 2 * p, nc = na + 1;
                #pragma unroll
                for (int j = 0; j < 4; ++j) {
                    if (na < N_NODES) dst[na * 320 + 128 + (u0 + j) * 3 + i] = lo[j] * sc;
                    if (nc < N_NODES) dst[nc * 320 + 128 + (u0 + j) * 3 + i] = hi[j] * sc;
                }
            }
        }
    }
}

// ---------------------------------------------------------------------------
// Kernel B (R8-proven, frozen): register-resident Wtp GEMMs fused with scatter.
// 64 edges/block, 256 threads; warp<->8 sorted edges, lanes<->channels.
// ---------------------------------------------------------------------------
__global__ void __launch_bounds__(256) edge_kernel(
    const float* __restrict__ edge_attr, const float* __restrict__ esa,
    const float* __restrict__ M1, const float* __restrict__ M2,
    const float* __restrict__ Wtp0, const float* __restrict__ Wtp1,
    const float* __restrict__ Wtp2, const float* __restrict__ Wtp3,
    const int* __restrict__ esrc, const int* __restrict__ edst)
{
    extern __shared__ float sm[];
    float* sInT = sm;             // 8 x 64
    float* sH1T = sm + 512;       // 64 x 64  [chan][edge]
    float* sH2T = sH1T + 4096;    // 64 x 64  [chan][edge]
    int*   sSrc = (int*)(sH2T + 4096);
    int*   sDst = sSrc + 64;
    float* sY   = (float*)(sDst + 64);

    const int tid = threadIdx.x;
    const int eb  = blockIdx.x * 64;

    for (int idx = tid; idx < 512; idx += 256) {
        int el = idx >> 3, k = idx & 7;
        int e = __ldg(&g_perm[eb + el]);
        sInT[k * 64 + el] = esa[e * 8 + k];
    }
    if (tid < 64) {
        int e = __ldg(&g_perm[eb + tid]);
        sSrc[tid] = esrc[e];
        sDst[tid] = edst[e];
        float4 y = *(const float4*)&edge_attr[e * 4];
        sY[tid * 4 + 0] = y.x; sY[tid * 4 + 1] = y.y;
        sY[tid * 4 + 2] = y.z; sY[tid * 4 + 3] = y.w;
    }
    __syncthreads();

    // h1 = gelu((esa @ M1)/sqrt(8))
    for (int idx = tid; idx < 4096; idx += 256) {
        int u = idx >> 6, el = idx & 63;
        float s = 0.f;
        #pragma unroll
        for (int k = 0; k < 8; ++k) s += sInT[k * 64 + el] * __ldg(&M1[k * 64 + u]);
        sH1T[idx] = gelu_tanh(s * 0.3535533905932738f);
    }
    __syncthreads();

    // h2 = gelu((h1 @ M2)/sqrt(64)), M2 straight from gmem
    {
        const int e0 = (tid & 15) * 4, u0 = (tid >> 4) * 4;
        u64 acc[4][2] = {};
        #pragma unroll 4
        for (int k = 0; k < 64; ++k) {
            float4 a = *(const float4*)&sH1T[k * 64 + e0];
            u64 ad0 = dupf(a.x), ad1 = dupf(a.y), ad2 = dupf(a.z), ad3 = dupf(a.w);
            ulonglong2 b = __ldg((const ulonglong2*)&M2[k * 64 + u0]);
            FFMA2(acc[0][0], ad0, b.x, acc[0][0]); FFMA2(acc[0][1], ad0, b.y, acc[0][1]);
            FFMA2(acc[1][0], ad1, b.x, acc[1][0]); FFMA2(acc[1][1], ad1, b.y, acc[1][1]);
            FFMA2(acc[2][0], ad2, b.x, acc[2][0]); FFMA2(acc[2][1], ad2, b.y, acc[2][1]);
            FFMA2(acc[3][0], ad3, b.x, acc[3][0]); FFMA2(acc[3][1], ad3, b.y, acc[3][1]);
        }
        #pragma unroll
        for (int e = 0; e < 4; ++e)
            #pragma unroll
            for (int j = 0; j < 2; ++j) {
                float lo, hi; unpack2(acc[e][j], lo, hi);
                sH2T[(u0 + 2*j    ) * 64 + e0 + e] = gelu_tanh(lo * 0.125f);
                sH2T[(u0 + 2*j + 1) * 64 + e0 + e] = gelu_tanh(hi * 0.125f);
            }
    }
    __syncthreads();

    // ============ barrier-free fused phases ============
    const int wid = tid >> 5, lane = tid & 31;
    const int we0 = wid * 8;

    // ---- p0: w0 -> mid0a (run-accumulated) ----
    {
        u64 acc[4][4] = {};
        #pragma unroll 4
        for (int k = 0; k < 64; ++k) {
            const float* ap = &sH2T[k * 64 + we0];
            ulonglong2 aa0 = *(const ulonglong2*)(ap);
            ulonglong2 aa1 = *(const ulonglong2*)(ap + 4);
            u64 a0 = aa0.x, a1 = aa0.y, a2 = aa1.x, a3 = aa1.y;
            float4 b = __ldg((const float4*)&Wtp0[k * 128 + lane * 4]);
            u64 b0 = dupf(b.x), b1 = dupf(b.y), b2 = dupf(b.z), b3 = dupf(b.w);
            FFMA2(acc[0][0], a0, b0, acc[0][0]); FFMA2(acc[0][1], a0, b1, acc[0][1]);
            FFMA2(acc[0][2], a0, b2, acc[0][2]); FFMA2(acc[0][3], a0, b3, acc[0][3]);
            FFMA2(acc[1][0], a1, b0, acc[1][0]); FFMA2(acc[1][1], a1, b1, acc[1][1]);
            FFMA2(acc[1][2], a1, b2, acc[1][2]); FFMA2(acc[1][3], a1, b3, acc[1][3]);
            FFMA2(acc[2][0], a2, b0, acc[2][0]); FFMA2(acc[2][1], a2, b1, acc[2][1]);
            FFMA2(acc[2][2], a2, b2, acc[2][2]); FFMA2(acc[2][3], a2, b3, acc[2][3]);
            FFMA2(acc[3][0], a3, b0, acc[3][0]); FFMA2(acc[3][1], a3, b1, acc[3][1]);
            FFMA2(acc[3][2], a3, b2, acc[3][2]); FFMA2(acc[3][3], a3, b3, acc[3][3]);
        }
        int cur = sDst[we0];
        float4 av = make_float4(0.f, 0.f, 0.f, 0.f);
        #pragma unroll
        for (int p = 0; p < 4; ++p) {
            float lo[4], hi[4];
            #pragma unroll
            for (int j = 0; j < 4; ++j) unpack2(acc[p][j], lo[j], hi[j]);
            #pragma unroll
            for (int h = 0; h < 2; ++h) {
                int e = we0 + 2 * p + h;
                int dst = sDst[e];
                if (dst != cur) {
                    red4(&g_agg[cur * 768 + lane * 4], av);
                    av = make_float4(0.f, 0.f, 0.f, 0.f);
                    cur = dst;
                }
                float y0 = sY[e * 4] * 0.125f;
                float4 f = *(const float4*)&g_feat[sSrc[e] * 320 + lane * 4];
                float wa = h ? hi[0] : lo[0], wb = h ? hi[1] : lo[1];
                float wc = h ? hi[2] : lo[2], wd = h ? hi[3] : lo[3];
                av.x += wa*f.x*y0; av.y += wb*f.y*y0;
                av.z += wc*f.z*y0; av.w += wd*f.w*y0;
            }
        }
        red4(&g_agg[cur * 768 + lane * 4], av);
    }

    // ---- p1: w1 -> mid1a (run-accumulated) ----
    {
        u64 acc[4][4] = {};
        #pragma unroll 4
        for (int k = 0; k < 64; ++k) {
            const float* ap = &sH2T[k * 64 + we0];
            ulonglong2 aa0 = *(const ulonglong2*)(ap);
            ulonglong2 aa1 = *(const ulonglong2*)(ap + 4);
            u64 a0 = aa0.x, a1 = aa0.y, a2 = aa1.x, a3 = aa1.y;
            float4 b = __ldg((const float4*)&Wtp1[k * 128 + lane * 4]);
            u64 b0 = dupf(b.x), b1 = dupf(b.y), b2 = dupf(b.z), b3 = dupf(b.w);
            FFMA2(acc[0][0], a0, b0, acc[0][0]); FFMA2(acc[0][1], a0, b1, acc[0][1]);
            FFMA2(acc[0][2], a0, b2, acc[0][2]); FFMA2(acc[0][3], a0, b3, acc[0][3]);
            FFMA2(acc[1][0], a1, b0, acc[1][0]); FFMA2(acc[1][1], a1, b1, acc[1][1]);
            FFMA2(acc[1][2], a1, b2, acc[1][2]); FFMA2(acc[1][3], a1, b3, acc[1][3]);
            FFMA2(acc[2][0], a2, b0, acc[2][0]); FFMA2(acc[2][1], a2, b1, acc[2][1]);
            FFMA2(acc[2][2], a2, b2, acc[2][2]); FFMA2(acc[2][3], a2, b3, acc[2][3]);
            FFMA2(acc[3][0], a3, b0, acc[3][0]); FFMA2(acc[3][1], a3, b1, acc[3][1]);
            FFMA2(acc[3][2], a3, b2, acc[3][2]); FFMA2(acc[3][3], a3, b3, acc[3][3]);
        }
        int cur = sDst[we0];
        float a[12];
        #pragma unroll
        for (int j = 0; j < 12; ++j) a[j] = 0.f;
        #pragma unroll
        for (int p = 0; p < 4; ++p) {
            float lo[4], hi[4];
            #pragma unroll
            for (int j = 0; j < 4; ++j) unpack2(acc[p][j], lo[j], hi[j]);
            #pragma unroll
            for (int h = 0; h < 2; ++h) {
                int e = we0 + 2 * p + h;
                int dst = sDst[e];
                if (dst != cur) {
                    float* bp = &g_agg[cur * 768 + 192 + lane * 12];
                    red4(bp,     make_float4(a[0], a[1], a[2],  a[3]));
                    red4(bp + 4, make_float4(a[4], a[5], a[6],  a[7]));
                    red4(bp + 8, make_float4(a[8], a[9], a[10], a[11]));
                    #pragma unroll
                    for (int j = 0; j < 12; ++j) a[j] = 0.f;
                    cur = dst;
                }
                float ya = sY[e*4+1] * 0.125f, yb = sY[e*4+2] * 0.125f, yc = sY[e*4+3] * 0.125f;
                float4 f = *(const float4*)&g_feat[sSrc[e] * 320 + lane * 4];
                float wa = h ? hi[0] : lo[0], wb = h ? hi[1] : lo[1];
                float wc = h ? hi[2] : lo[2], wd = h ? hi[3] : lo[3];
                float t0 = wa*f.x, t1 = wb*f.y, t2 = wc*f.z, t3 = wd*f.w;
                a[0] += t0*ya; a[1]  += t0*yb; a[2]  += t0*yc;
                a[3] += t1*ya; a[4]  += t1*yb; a[5]  += t1*yc;
                a[6] += t2*ya; a[7]  += t2*yb; a[8]  += t2*yc;
                a[9] += t3*ya; a[10] += t3*yb; a[11] += t3*yc;
            }
        }
        float* bp = &g_agg[cur * 768 + 192 + lane * 12];
        red4(bp,     make_float4(a[0], a[1], a[2],  a[3]));
        red4(bp + 4, make_float4(a[4], a[5], a[6],  a[7]));
        red4(bp + 8, make_float4(a[8], a[9], a[10], a[11]));
    }

    // ---- p2+p3: w2 -> mid1b, w3 -> mid0b (run-accumulated) ----
    {
        u64 ac2[4][2] = {}, ac3[4][2] = {};
        #pragma unroll 4
        for (int k = 0; k < 64; ++k) {
            const float* ap = &sH2T[k * 64 + we0];
            ulonglong2 aa0 = *(const ulonglong2*)(ap);
            ulonglong2 aa1 = *(const ulonglong2*)(ap + 4);
            u64 a0 = aa0.x, a1 = aa0.y, a2 = aa1.x, a3 = aa1.y;
            float2 b2v = __ldg((const float2*)&Wtp2[k * 64 + lane * 2]);
            float2 b3v = __ldg((const float2*)&Wtp3[k * 64 + lane * 2]);
            u64 b20 = dupf(b2v.x), b21 = dupf(b2v.y);
            u64 b30 = dupf(b3v.x), b31 = dupf(b3v.y);
            FFMA2(ac2[0][0], a0, b20, ac2[0][0]); FFMA2(ac2[0][1], a0, b21, ac2[0][1]);
            FFMA2(ac2[1][0], a1, b20, ac2[1][0]); FFMA2(ac2[1][1], a1, b21, ac2[1][1]);
            FFMA2(ac2[2][0], a2, b20, ac2[2][0]); FFMA2(ac2[2][1], a2, b21, ac2[2][1]);
            FFMA2(ac2[3][0], a3, b20, ac2[3][0]); FFMA2(ac2[3][1], a3, b21, ac2[3][1]);
            FFMA2(ac3[0][0], a0, b30, ac3[0][0]); FFMA2(ac3[0][1], a0, b31, ac3[0][1]);
            FFMA2(ac3[1][0], a1, b30, ac3[1][0]); FFMA2(ac3[1][1], a1, b31, ac3[1][1]);
            FFMA2(ac3[2][0], a2, b30, ac3[2][0]); FFMA2(ac3[2][1], a2, b31, ac3[2][1]);
            FFMA2(ac3[3][0], a3, b30, ac3[3][0]); FFMA2(ac3[3][1], a3, b31, ac3[3][1]);
        }
        const float k3 = 0.125f * 0.5773502691896258f;
        int cur = sDst[we0];
        float q2[6] = {0.f, 0.f, 0.f, 0.f, 0.f, 0.f};
        float q3[2] = {0.f, 0.f};
        #pragma unroll
        for (int p = 0; p < 4; ++p) {
            float lo20, hi20, lo21, hi21, lo30, hi30, lo31, hi31;
            unpack2(ac2[p][0], lo20, hi20); unpack2(ac2[p][1], lo21, hi21);
            unpack2(ac3[p][0], lo30, hi30); unpack2(ac3[p][1], lo31, hi31);
            #pragma unroll
            for (int h = 0; h < 2; ++h) {
                int e = we0 + 2 * p + h;
                int dst = sDst[e];
                if (dst != cur) {
                    float* bp = &g_agg[cur * 768 + 576 + lane * 6];
                    red2(bp,     q2[0], q2[1]);
                    red2(bp + 2, q2[2], q2[3]);
                    red2(bp + 4, q2[4], q2[5]);
                    red2(&g_agg[cur * 768 + 128 + lane * 2], q3[0] * k3, q3[1] * k3);
                    #pragma unroll
                    for (int j = 0; j < 6; ++j) q2[j] = 0.f;
                    q3[0] = 0.f; q3[1] = 0.f;
                    cur = dst;
                }
                float y0 = sY[e*4] * 0.125f;
                float ya = sY[e*4+1], yb = sY[e*4+2], yc = sY[e*4+3];
                const float* fb = &g_feat[sSrc[e] * 320 + 128 + lane * 6];
                float2 f0 = *(const float2*)fb;
                float2 f1 = *(const float2*)(fb + 2);
                float2 f2 = *(const float2*)(fb + 4);
                float w2x = h ? hi20 : lo20, w2y = h ? hi21 : lo21;
                float w3x = h ? hi30 : lo30, w3y = h ? hi31 : lo31;
                q2[0] += w2x*f0.x*y0; q2[1] += w2x*f0.y*y0; q2[2] += w2x*f1.x*y0;
                q2[3] += w2y*f1.y*y0; q2[4] += w2y*f2.x*y0; q2[5] += w2y*f2.y*y0;
                float d0 = f0.x*ya + f0.y*yb + f1.x*yc;
                float d1 = f1.y*ya + f2.x*yb + f2.y*yc;
                q3[0] += w3x*d0; q3[1] += w3y*d1;
            }
        }
        float* bp = &g_agg[cur * 768 + 576 + lane * 6];
        red2(bp,     q2[0], q2[1]);
        red2(bp + 2, q2[2], q2[3]);
        red2(bp + 4, q2[4], q2[5]);
        red2(&g_agg[cur * 768 + 128 + lane * 2], q3[0] * k3, q3[1] * k3);
    }
}

// ---------------------------------------------------------------------------
// Kernel D (R12-proven, full weight stage): output transforms.
// ---------------------------------------------------------------------------
__global__ void __launch_bounds__(256) node_out_kernel(
    const float* __restrict__ Wo0, const float* __restrict__ Wo1,
    float* __restrict__ out)
{
    extern __shared__ float sm[];
    float* zT = sm;              // 192 x 34
    float* sW = sm + 192 * 34;   // 192 x 64
    const int tid = threadIdx.x;
    const int nb  = blockIdx.x * 32;
    const int n0 = (tid >> 5) * 4;
    const int u0 = (tid & 31) * 2;
    const float cs    = 0.9238795325112867f;
    const float kconv = 0.38268343236508984f * 0.25f * 0.07216878364870323f;

    for (int idx = tid; idx < 32 * 192; idx += 256) {
        int n = idx / 192, k = idx % 192;
        zT[k * 34 + n] = (nb + n < N_NODES) ? g_agg[(nb + n) * 768 + k] : 0.f;
    }
    for (int uc = 0; uc < 128; uc += 64) {
        __syncthreads();
        for (int idx = tid; idx < 192 * 64; idx += 256) {
            int k = idx >> 6, u = idx & 63;
            sW[idx] = Wo0[k * 128 + uc + u];
        }
        __syncthreads();
        u64 acc[2][2] = {};
        #pragma unroll 4
        for (int k = 0; k < 192; ++k) {
            u64 a01 = *(const u64*)&zT[k * 34 + n0];
            u64 a23 = *(const u64*)&zT[k * 34 + n0 + 2];
            float2 b = *(const float2*)&sW[k * 64 + u0];
            u64 b0 = dupf(b.x), b1 = dupf(b.y);
            FFMA2(acc[0][0], a01, b0, acc[0][0]); FFMA2(acc[0][1], a01, b1, acc[0][1]);
            FFMA2(acc[1][0], a23, b0, acc[1][0]); FFMA2(acc[1][1], a23, b1, acc[1][1]);
        }
        #pragma unroll
        for (int p = 0; p < 2; ++p) {
            float lo[2], hi[2];
            unpack2(acc[p][0], lo[0], hi[0]);
            unpack2(acc[p][1], lo[1], hi[1]);
            int na = nb + n0 + 2 * p, nc = na + 1;
            if (na < N_NODES) {
                const float* sf = &g_self[na * 320 + uc + u0];
                *(float2*)&out[na * 320 + uc + u0] =
                    make_float2(cs*sf[0] + kconv*lo[0], cs*sf[1] + kconv*lo[1]);
            }
            if (nc < N_NODES) {
                const float* sf = &g_self[nc * 320 + uc + u0];
                *(float2*)&out[nc * 320 + uc + u0] =
                    make_float2(cs*sf[0] + kconv*hi[0], cs*sf[1] + kconv*hi[1]);
            }
        }
    }

    __syncthreads();
    for (int idx = tid; idx < 192 * 64; idx += 256) sW[idx] = Wo1[idx];
    for (int i = 0; i < 3; ++i) {
        __syncthreads();
        for (int idx = tid; idx < 32 * 192; idx += 256) {
            int n = idx / 192, k = idx % 192;
            zT[k * 34 + n] = (nb + n < N_NODES) ? g_agg[(nb + n) * 768 + 192 + k * 3 + i] : 0.f;
        }
        __syncthreads();
        u64 acc[2][2] = {};
        #pragma unroll 4
        for (int k = 0; k < 192; ++k) {
            u64 a01 = *(const u64*)&zT[k * 34 + n0];
            u64 a23 = *(const u64*)&zT[k * 34 + n0 + 2];
            float2 b = *(const float2*)&sW[k * 64 + u0];
            u64 b0 = dupf(b.x), b1 = dupf(b.y);
            FFMA2(acc[0][0], a01, b0, acc[0][0]); FFMA2(acc[0][1], a01, b1, acc[0][1]);
            FFMA2(acc[1][0], a23, b0, acc[1][0]); FFMA2(acc[1][1], a23, b1, acc[1][1]);
        }
        #pragma unroll
        for (int p = 0; p < 2; ++p) {
            float lo[2], hi[2];
            unpack2(acc[p][0], lo[0], hi[0]);
            unpack2(acc[p][1], lo[1], hi[1]);
            int na = nb + n0 + 2 * p, nc = na + 1;
            #pragma unroll
            for (int j = 0; j < 2; ++j) {
                if (na < N_NODES)
                    out[na * 320 + 128 + (u0 + j) * 3 + i] =
                        cs * g_self[na * 320 + 128 + (u0 + j) * 3 + i] + kconv * lo[j];
                if (nc < N_NODES)
                    out[nc * 320 + 128 + (u0 + j) * 3 + i] =
                        cs * g_self[nc * 320 + 128 + (u0 + j) * 3 + i] + kconv * hi[j];
            }
        }
    }
}

// ---------------------------------------------------------------------------
extern "C" void kernel_launch(void* const* d_in, const int* in_sizes, int n_in,
                              void* d_out, int out_size)
{
    const float* node = (const float*)d_in[0];
    const float* edge_attr = (const float*)d_in[1];
    const float* esa  = (const float*)d_in[2];
    const float* Wa0  = (const float*)d_in[3];
    const float* Wa1  = (const float*)d_in[4];
    const float* Wb0  = (const float*)d_in[5];
    const float* Wb1  = (const float*)d_in[6];
    const float* M1   = (const float*)d_in[7];
    const float* M2   = (const float*)d_in[8];
    const float* Wtp0 = (const float*)d_in[9];
    const float* Wtp1 = (const float*)d_in[10];
    const float* Wtp2 = (const float*)d_in[11];
    const float* Wtp3 = (const float*)d_in[12];
    const float* Wo0  = (const float*)d_in[13];
    const float* Wo1  = (const float*)d_in[14];
    const int* esrc   = (const int*)d_in[15];
    const int* edst   = (const int*)d_in[16];
    float* out = (float*)d_out;

    const int smemA = (320 * 34 + 64 * 128) * 4;                           // 76288
    const int smemB = (512 + 4096 + 4096) * 4 + 64 * 4 * 2 + 64 * 4 * 4;   // 36352
    const int smemD = (192 * 34 + 192 * 64) * 4;                           // 75264

    cudaFuncSetAttribute(node_pre_kernel, cudaFuncAttributeMaxDynamicSharedMemorySize, smemA);
    cudaFuncSetAttribute(edge_kernel,     cudaFuncAttributeMaxDynamicSharedMemorySize, smemB);
    cudaFuncSetAttribute(node_out_kernel, cudaFuncAttributeMaxDynamicSharedMemorySize, smemD);

    void *aggp = nullptr, *cntp = nullptr;
    cudaGetSymbolAddress(&aggp, g_agg);
    cudaGetSymbolAddress(&cntp, g_cnt);
    cudaMemsetAsync(aggp, 0, sizeof(float) * (size_t)N_NODES * AGG_DIM);
    cudaMemsetAsync(cntp, 0, sizeof(int) * N_NODES);

    hist_kernel<<<(N_EDGES + 255) / 256, 256>>>(edst);
    scan_kernel<<<1, 1024>>>();
    scatter_kernel<<<(N_EDGES + 255) / 256, 256>>>(edst);

    node_pre_kernel<<<(N_NODES + 31) / 32, 256, smemA>>>(node, Wa0, Wa1, Wb0, Wb1);
    edge_kernel<<<N_EDGES / 64, 256, smemB>>>(edge_attr, esa, M1, M2,
                                              Wtp0, Wtp1, Wtp2, Wtp3, esrc, edst);
    node_out_kernel<<<(N_NODES + 31) / 32, 256, smemD>>>(Wo0, Wo1, out);
}

// round 16
// speedup vs baseline: 1.1784x; 1.0074x over previous
#include <cuda_runtime.h>
#include <math.h>

#define N_NODES 10000
#define N_EDGES 160000
#define FEAT_DIM 320
#define AGG_DIM 768

typedef unsigned long long u64;

__device__ float g_feat[N_NODES * FEAT_DIM];
__device__ float g_self[N_NODES * FEAT_DIM];
__device__ float g_agg [N_NODES * AGG_DIM];
// counting-sort scratch
__device__ int g_cnt [N_NODES];
__device__ int g_off [N_NODES];   // exclusive prefix; consumed (destructively) by scatter
__device__ int g_perm[N_EDGES];

__device__ __forceinline__ float gelu_tanh(float x) {
    float x3 = x * x * x;
    float z  = 0.7978845608028654f * (x + 0.044715f * x3);
    float t;
    asm("tanh.approx.f32 %0, %1;" : "=f"(t) : "f"(z));
    return 0.5f * x * (1.0f + t);
}

__device__ __forceinline__ void red4(float* p, float4 v) {
    asm volatile("red.global.add.v4.f32 [%0], {%1,%2,%3,%4};"
                 :: "l"(p), "f"(v.x), "f"(v.y), "f"(v.z), "f"(v.w) : "memory");
}
__device__ __forceinline__ void red2(float* p, float a, float b) {
    asm volatile("red.global.add.v2.f32 [%0], {%1,%2};"
                 :: "l"(p), "f"(a), "f"(b) : "memory");
}

__device__ __forceinline__ u64 dupf(float x) {
    u64 r; asm("mov.b64 %0, {%1, %1};" : "=l"(r) : "f"(x)); return r;
}
__device__ __forceinline__ void unpack2(u64 v, float& lo, float& hi) {
    asm("mov.b64 {%0, %1}, %2;" : "=f"(lo), "=f"(hi) : "l"(v));
}
#define FFMA2(d, a, b, c) asm("fma.rn.f32x2 %0, %1, %2, %3;" : "=l"(d) : "l"(a), "l"(b), "l"(c))

// ---------------------------------------------------------------------------
// Counting sort of edges by dst (g_off doubles as the fill cursor)
// ---------------------------------------------------------------------------
__global__ void hist_kernel(const int* __restrict__ edst) {
    int e = blockIdx.x * 256 + threadIdx.x;
    if (e < N_EDGES) atomicAdd(&g_cnt[edst[e]], 1);
}

__global__ void __launch_bounds__(1024) scan_kernel() {
    __shared__ int part[1024];
    const int t = threadIdx.x;
    const int base = t * 10;
    int local[10];
    int s = 0;
    #pragma unroll
    for (int j = 0; j < 10; ++j) {
        int idx = base + j;
        int c = (idx < N_NODES) ? g_cnt[idx] : 0;
        local[j] = s; s += c;
    }
    part[t] = s;
    __syncthreads();
    for (int off = 1; off < 1024; off <<= 1) {
        int v = (t >= off) ? part[t - off] : 0;
        __syncthreads();
        part[t] += v;
        __syncthreads();
    }
    int pre = (t == 0) ? 0 : part[t - 1];
    #pragma unroll
    for (int j = 0; j < 10; ++j) {
        int idx = base + j;
        if (idx < N_NODES) g_off[idx] = pre + local[j];
    }
}

__global__ void scatter_kernel(const int* __restrict__ edst) {
    int e = blockIdx.x * 256 + threadIdx.x;
    if (e < N_EDGES) {
        int pos = atomicAdd(&g_off[edst[e]], 1);   // destructive: g_off is the cursor
        g_perm[pos] = e;
    }
}

// ---------------------------------------------------------------------------
// Kernel A (R12-proven): 32 nodes/block, 256 threads. Weights staged in
// k-chunks of 64 (sW 32KB) -> total smem 76.3KB -> 3 CTAs/SM.
// ---------------------------------------------------------------------------
__global__ void __launch_bounds__(256) node_pre_kernel(
    const float* __restrict__ node,
    const float* __restrict__ Wa0, const float* __restrict__ Wa1,
    const float* __restrict__ Wb0, const float* __restrict__ Wb1)
{
    extern __shared__ float sm[];
    float* xT = sm;               // 320 x 34  (43520 B)
    float* sW = sm + 320 * 34;    // 64 x 128  (32768 B)
    const int tid = threadIdx.x;
    const int nb  = blockIdx.x * 32;

    for (int idx = tid; idx < 32 * 320; idx += 256) {
        int n = idx / 320, k = idx % 320;
        float v = (nb + n < N_NODES) ? node[(nb + n) * 320 + k] : 0.f;
        xT[k * 34 + n] = v;
    }

    const int n0s = (tid >> 5) * 4;
    const int u0s = (tid & 31) * 4;
    for (int w = 0; w < 2; ++w) {
        const float* W = w ? Wb0 : Wa0;
        float* dst     = w ? g_self : g_feat;
        u64 acc[2][4] = {};
        for (int kc = 0; kc < 2; ++kc) {
            __syncthreads();
            for (int idx = tid; idx < 2048; idx += 256)
                ((float4*)sW)[idx] = ((const float4*)W)[kc * 2048 + idx];
            __syncthreads();
            #pragma unroll 4
            for (int k = 0; k < 64; ++k) {
                int kk = kc * 64 + k;
                u64 a01 = *(const u64*)&xT[kk * 34 + n0s];
                u64 a23 = *(const u64*)&xT[kk * 34 + n0s + 2];
                float4 b = *(const float4*)&sW[k * 128 + u0s];
                u64 b0 = dupf(b.x), b1 = dupf(b.y), b2 = dupf(b.z), b3 = dupf(b.w);
                FFMA2(acc[0][0], a01, b0, acc[0][0]); FFMA2(acc[0][1], a01, b1, acc[0][1]);
                FFMA2(acc[0][2], a01, b2, acc[0][2]); FFMA2(acc[0][3], a01, b3, acc[0][3]);
                FFMA2(acc[1][0], a23, b0, acc[1][0]); FFMA2(acc[1][1], a23, b1, acc[1][1]);
                FFMA2(acc[1][2], a23, b2, acc[1][2]); FFMA2(acc[1][3], a23, b3, acc[1][3]);
            }
        }
        const float sc = 0.08838834764831845f;
        #pragma unroll
        for (int p = 0; p < 2; ++p) {
            float lo[4], hi[4];
            #pragma unroll
            for (int j = 0; j < 4; ++j) unpack2(acc[p][j], lo[j], hi[j]);
            int na = nb + n0s + 2 * p, nc = na + 1;
            if (na < N_NODES)
                *(float4*)&dst[na * 320 + u0s] = make_float4(lo[0]*sc, lo[1]*sc, lo[2]*sc, lo[3]*sc);
            if (nc < N_NODES)
                *(float4*)&dst[nc * 320 + u0s] = make_float4(hi[0]*sc, hi[1]*sc, hi[2]*sc, hi[3]*sc);
        }
    }

    // ---- vector part: Wa1 (half 0) and Wb1 (half 1) concurrently ----
    __syncthreads();
    for (int idx = tid; idx < 1024; idx += 256) ((float4*)sW)[idx] = ((const float4*)Wa1)[idx];
    for (int idx = tid; idx < 1024; idx += 256) ((float4*)(sW + 4096))[idx] = ((const float4*)Wb1)[idx];
    __syncthreads();
    {
        const int half = tid >> 7;
        const int wt   = tid & 127;
        const int n0   = (wt >> 4) * 4;
        const int u0   = (wt & 15) * 4;
        const float* sWh = sW + half * 4096;
        float* dst       = half ? g_self : g_feat;
        for (int i = 0; i < 3; ++i) {
            u64 acc[2][4] = {};
            #pragma unroll 4
            for (int v = 0; v < 64; ++v) {
                int k = 128 + v * 3 + i;
                u64 a01 = *(const u64*)&xT[k * 34 + n0];
                u64 a23 = *(const u64*)&xT[k * 34 + n0 + 2];
                float4 b = *(const float4*)&sWh[v * 64 + u0];
                u64 b0 = dupf(b.x), b1 = dupf(b.y), b2 = dupf(b.z), b3 = dupf(b.w);
                FFMA2(acc[0][0], a01, b0, acc[0][0]); FFMA2(acc[0][1], a01, b1, acc[0][1]);
                FFMA2(acc[0][2], a01, b2, acc[0][2]); FFMA2(acc[0][3], a01, b3, acc[0][3]);
                FFMA2(acc[1][0], a23, b0, acc[1][0]); FFMA2(acc[1][1], a23, b1, acc[1][1]);
                FFMA2(acc[1][2], a23, b2, acc[1][2]); FFMA2(acc[1][3], a23, b3, acc[1][3]);
            }
            const float sc = 0.125f;
            #pragma unroll
            for (int p = 0; p < 2; ++p) {
                float lo[4], hi[4];
                #pragma unroll
                for (int j = 0; j < 4; ++j) unpack2(acc[p][j], lo[j], hi[j]);
                int na = nb + n0 + 2 * p, nc = na + 1;
                #pragma unroll
                for (int j = 0; j < 4; ++j) {
                    if (na < N_NODES) dst[na * 320 + 128 + (u0 + j) * 3 + i] = lo[j] * sc;
                    if (nc < N_NODES) dst[nc * 320 + 128 + (u0 + j) * 3 + i] = hi[j] * sc;
                }
            }
        }
    }
}

// ---------------------------------------------------------------------------
// Kernel B: R8-proven structure; NEW: min 3 CTAs/SM via launch bounds
// (registers were the occupancy limiter; smem is only 36KB).
// ---------------------------------------------------------------------------
__global__ void __launch_bounds__(256, 3) edge_kernel(
    const float* __restrict__ edge_attr, const float* __restrict__ esa,
    const float* __restrict__ M1, const float* __restrict__ M2,
    const float* __restrict__ Wtp0, const float* __restrict__ Wtp1,
    const float* __restrict__ Wtp2, const float* __restrict__ Wtp3,
    const int* __restrict__ esrc, const int* __restrict__ edst)
{
    extern __shared__ float sm[];
    float* sInT = sm;             // 8 x 64
    float* sH1T = sm + 512;       // 64 x 64  [chan][edge]
    float* sH2T = sH1T + 4096;    // 64 x 64  [chan][edge]
    int*   sSrc = (int*)(sH2T + 4096);
    int*   sDst = sSrc + 64;
    float* sY   = (float*)(sDst + 64);

    const int tid = threadIdx.x;
    const int eb  = blockIdx.x * 64;

    for (int idx = tid; idx < 512; idx += 256) {
        int el = idx >> 3, k = idx & 7;
        int e = __ldg(&g_perm[eb + el]);
        sInT[k * 64 + el] = esa[e * 8 + k];
    }
    if (tid < 64) {
        int e = __ldg(&g_perm[eb + tid]);
        sSrc[tid] = esrc[e];
        sDst[tid] = edst[e];
        float4 y = *(const float4*)&edge_attr[e * 4];
        sY[tid * 4 + 0] = y.x; sY[tid * 4 + 1] = y.y;
        sY[tid * 4 + 2] = y.z; sY[tid * 4 + 3] = y.w;
    }
    __syncthreads();

    // h1 = gelu((esa @ M1)/sqrt(8))
    for (int idx = tid; idx < 4096; idx += 256) {
        int u = idx >> 6, el = idx & 63;
        float s = 0.f;
        #pragma unroll
        for (int k = 0; k < 8; ++k) s += sInT[k * 64 + el] * __ldg(&M1[k * 64 + u]);
        sH1T[idx] = gelu_tanh(s * 0.3535533905932738f);
    }
    __syncthreads();

    // h2 = gelu((h1 @ M2)/sqrt(64)), M2 straight from gmem
    {
        const int e0 = (tid & 15) * 4, u0 = (tid >> 4) * 4;
        u64 acc[4][2] = {};
        #pragma unroll 4
        for (int k = 0; k < 64; ++k) {
            float4 a = *(const float4*)&sH1T[k * 64 + e0];
            u64 ad0 = dupf(a.x), ad1 = dupf(a.y), ad2 = dupf(a.z), ad3 = dupf(a.w);
            ulonglong2 b = __ldg((const ulonglong2*)&M2[k * 64 + u0]);
            FFMA2(acc[0][0], ad0, b.x, acc[0][0]); FFMA2(acc[0][1], ad0, b.y, acc[0][1]);
            FFMA2(acc[1][0], ad1, b.x, acc[1][0]); FFMA2(acc[1][1], ad1, b.y, acc[1][1]);
            FFMA2(acc[2][0], ad2, b.x, acc[2][0]); FFMA2(acc[2][1], ad2, b.y, acc[2][1]);
            FFMA2(acc[3][0], ad3, b.x, acc[3][0]); FFMA2(acc[3][1], ad3, b.y, acc[3][1]);
        }
        #pragma unroll
        for (int e = 0; e < 4; ++e)
            #pragma unroll
            for (int j = 0; j < 2; ++j) {
                float lo, hi; unpack2(acc[e][j], lo, hi);
                sH2T[(u0 + 2*j    ) * 64 + e0 + e] = gelu_tanh(lo * 0.125f);
                sH2T[(u0 + 2*j + 1) * 64 + e0 + e] = gelu_tanh(hi * 0.125f);
            }
    }
    __syncthreads();

    // ============ barrier-free fused phases ============
    const int wid = tid >> 5, lane = tid & 31;
    const int we0 = wid * 8;

    // ---- p0: w0 -> mid0a (run-accumulated) ----
    {
        u64 acc[4][4] = {};
        #pragma unroll 4
        for (int k = 0; k < 64; ++k) {
            const float* ap = &sH2T[k * 64 + we0];
            ulonglong2 aa0 = *(const ulonglong2*)(ap);
            ulonglong2 aa1 = *(const ulonglong2*)(ap + 4);
            u64 a0 = aa0.x, a1 = aa0.y, a2 = aa1.x, a3 = aa1.y;
            float4 b = __ldg((const float4*)&Wtp0[k * 128 + lane * 4]);
            u64 b0 = dupf(b.x), b1 = dupf(b.y), b2 = dupf(b.z), b3 = dupf(b.w);
            FFMA2(acc[0][0], a0, b0, acc[0][0]); FFMA2(acc[0][1], a0, b1, acc[0][1]);
            FFMA2(acc[0][2], a0, b2, acc[0][2]); FFMA2(acc[0][3], a0, b3, acc[0][3]);
            FFMA2(acc[1][0], a1, b0, acc[1][0]); FFMA2(acc[1][1], a1, b1, acc[1][1]);
            FFMA2(acc[1][2], a1, b2, acc[1][2]); FFMA2(acc[1][3], a1, b3, acc[1][3]);
            FFMA2(acc[2][0], a2, b0, acc[2][0]); FFMA2(acc[2][1], a2, b1, acc[2][1]);
            FFMA2(acc[2][2], a2, b2, acc[2][2]); FFMA2(acc[2][3], a2, b3, acc[2][3]);
            FFMA2(acc[3][0], a3, b0, acc[3][0]); FFMA2(acc[3][1], a3, b1, acc[3][1]);
            FFMA2(acc[3][2], a3, b2, acc[3][2]); FFMA2(acc[3][3], a3, b3, acc[3][3]);
        }
        int cur = sDst[we0];
        float4 av = make_float4(0.f, 0.f, 0.f, 0.f);
        #pragma unroll
        for (int p = 0; p < 4; ++p) {
            float lo[4], hi[4];
            #pragma unroll
            for (int j = 0; j < 4; ++j) unpack2(acc[p][j], lo[j], hi[j]);
            #pragma unroll
            for (int h = 0; h < 2; ++h) {
                int e = we0 + 2 * p + h;
                int dst = sDst[e];
                if (dst != cur) {
                    red4(&g_agg[cur * 768 + lane * 4], av);
                    av = make_float4(0.f, 0.f, 0.f, 0.f);
                    cur = dst;
                }
                float y0 = sY[e * 4] * 0.125f;
                float4 f = *(const float4*)&g_feat[sSrc[e] * 320 + lane * 4];
                float wa = h ? hi[0] : lo[0], wb = h ? hi[1] : lo[1];
                float wc = h ? hi[2] : lo[2], wd = h ? hi[3] : lo[3];
                av.x += wa*f.x*y0; av.y += wb*f.y*y0;
                av.z += wc*f.z*y0; av.w += wd*f.w*y0;
            }
        }
        red4(&g_agg[cur * 768 + lane * 4], av);
    }

    // ---- p1: w1 -> mid1a (run-accumulated) ----
    {
        u64 acc[4][4] = {};
        #pragma unroll 4
        for (int k = 0; k < 64; ++k) {
            const float* ap = &sH2T[k * 64 + we0];
            ulonglong2 aa0 = *(const ulonglong2*)(ap);
            ulonglong2 aa1 = *(const ulonglong2*)(ap + 4);
            u64 a0 = aa0.x, a1 = aa0.y, a2 = aa1.x, a3 = aa1.y;
            float4 b = __ldg((const float4*)&Wtp1[k * 128 + lane * 4]);
            u64 b0 = dupf(b.x), b1 = dupf(b.y), b2 = dupf(b.z), b3 = dupf(b.w);
            FFMA2(acc[0][0], a0, b0, acc[0][0]); FFMA2(acc[0][1], a0, b1, acc[0][1]);
            FFMA2(acc[0][2], a0, b2, acc[0][2]); FFMA2(acc[0][3], a0, b3, acc[0][3]);
            FFMA2(acc[1][0], a1, b0, acc[1][0]); FFMA2(acc[1][1], a1, b1, acc[1][1]);
            FFMA2(acc[1][2], a1, b2, acc[1][2]); FFMA2(acc[1][3], a1, b3, acc[1][3]);
            FFMA2(acc[2][0], a2, b0, acc[2][0]); FFMA2(acc[2][1], a2, b1, acc[2][1]);
            FFMA2(acc[2][2], a2, b2, acc[2][2]); FFMA2(acc[2][3], a2, b3, acc[2][3]);
            FFMA2(acc[3][0], a3, b0, acc[3][0]); FFMA2(acc[3][1], a3, b1, acc[3][1]);
            FFMA2(acc[3][2], a3, b2, acc[3][2]); FFMA2(acc[3][3], a3, b3, acc[3][3]);
        }
        int cur = sDst[we0];
        float a[12];
        #pragma unroll
        for (int j = 0; j < 12; ++j) a[j] = 0.f;
        #pragma unroll
        for (int p = 0; p < 4; ++p) {
            float lo[4], hi[4];
            #pragma unroll
            for (int j = 0; j < 4; ++j) unpack2(acc[p][j], lo[j], hi[j]);
            #pragma unroll
            for (int h = 0; h < 2; ++h) {
                int e = we0 + 2 * p + h;
                int dst = sDst[e];
                if (dst != cur) {
                    float* bp = &g_agg[cur * 768 + 192 + lane * 12];
                    red4(bp,     make_float4(a[0], a[1], a[2],  a[3]));
                    red4(bp + 4, make_float4(a[4], a[5], a[6],  a[7]));
                    red4(bp + 8, make_float4(a[8], a[9], a[10], a[11]));
                    #pragma unroll
                    for (int j = 0; j < 12; ++j) a[j] = 0.f;
                    cur = dst;
                }
                float ya = sY[e*4+1] * 0.125f, yb = sY[e*4+2] * 0.125f, yc = sY[e*4+3] * 0.125f;
                float4 f = *(const float4*)&g_feat[sSrc[e] * 320 + lane * 4];
                float wa = h ? hi[0] : lo[0], wb = h ? hi[1] : lo[1];
                float wc = h ? hi[2] : lo[2], wd = h ? hi[3] : lo[3];
                float t0 = wa*f.x, t1 = wb*f.y, t2 = wc*f.z, t3 = wd*f.w;
                a[0] += t0*ya; a[1]  += t0*yb; a[2]  += t0*yc;
                a[3] += t1*ya; a[4]  += t1*yb; a[5]  += t1*yc;
                a[6] += t2*ya; a[7]  += t2*yb; a[8]  += t2*yc;
                a[9] += t3*ya; a[10] += t3*yb; a[11] += t3*yc;
            }
        }
        float* bp = &g_agg[cur * 768 + 192 + lane * 12];
        red4(bp,     make_float4(a[0], a[1], a[2],  a[3]));
        red4(bp + 4, make_float4(a[4], a[5], a[6],  a[7]));
        red4(bp + 8, make_float4(a[8], a[9], a[10], a[11]));
    }

    // ---- p2+p3: w2 -> mid1b, w3 -> mid0b (run-accumulated) ----
    {
        u64 ac2[4][2] = {}, ac3[4][2] = {};
        #pragma unroll 4
        for (int k = 0; k < 64; ++k) {
            const float* ap = &sH2T[k * 64 + we0];
            ulonglong2 aa0 = *(const ulonglong2*)(ap);
            ulonglong2 aa1 = *(const ulonglong2*)(ap + 4);
            u64 a0 = aa0.x, a1 = aa0.y, a2 = aa1.x, a3 = aa1.y;
            float2 b2v = __ldg((const float2*)&Wtp2[k * 64 + lane * 2]);
            float2 b3v = __ldg((const float2*)&Wtp3[k * 64 + lane * 2]);
            u64 b20 = dupf(b2v.x), b21 = dupf(b2v.y);
            u64 b30 = dupf(b3v.x), b31 = dupf(b3v.y);
            FFMA2(ac2[0][0], a0, b20, ac2[0][0]); FFMA2(ac2[0][1], a0, b21, ac2[0][1]);
            FFMA2(ac2[1][0], a1, b20, ac2[1][0]); FFMA2(ac2[1][1], a1, b21, ac2[1][1]);
            FFMA2(ac2[2][0], a2, b20, ac2[2][0]); FFMA2(ac2[2][1], a2, b21, ac2[2][1]);
            FFMA2(ac2[3][0], a3, b20, ac2[3][0]); FFMA2(ac2[3][1], a3, b21, ac2[3][1]);
            FFMA2(ac3[0][0], a0, b30, ac3[0][0]); FFMA2(ac3[0][1], a0, b31, ac3[0][1]);
            FFMA2(ac3[1][0], a1, b30, ac3[1][0]); FFMA2(ac3[1][1], a1, b31, ac3[1][1]);
            FFMA2(ac3[2][0], a2, b30, ac3[2][0]); FFMA2(ac3[2][1], a2, b31, ac3[2][1]);
            FFMA2(ac3[3][0], a3, b30, ac3[3][0]); FFMA2(ac3[3][1], a3, b31, ac3[3][1]);
        }
        const float k3 = 0.125f * 0.5773502691896258f;
        int cur = sDst[we0];
        float q2[6] = {0.f, 0.f, 0.f, 0.f, 0.f, 0.f};
        float q3[2] = {0.f, 0.f};
        #pragma unroll
        for (int p = 0; p < 4; ++p) {
            float lo20, hi20, lo21, hi21, lo30, hi30, lo31, hi31;
            unpack2(ac2[p][0], lo20, hi20); unpack2(ac2[p][1], lo21, hi21);
            unpack2(ac3[p][0], lo30, hi30); unpack2(ac3[p][1], lo31, hi31);
            #pragma unroll
            for (int h = 0; h < 2; ++h) {
                int e = we0 + 2 * p + h;
                int dst = sDst[e];
                if (dst != cur) {
                    float* bp = &g_agg[cur * 768 + 576 + lane * 6];
                    red2(bp,     q2[0], q2[1]);
                    red2(bp + 2, q2[2], q2[3]);
                    red2(bp + 4, q2[4], q2[5]);
                    red2(&g_agg[cur * 768 + 128 + lane * 2], q3[0] * k3, q3[1] * k3);
                    #pragma unroll
                    for (int j = 0; j < 6; ++j) q2[j] = 0.f;
                    q3[0] = 0.f; q3[1] = 0.f;
                    cur = dst;
                }
                float y0 = sY[e*4] * 0.125f;
                float ya = sY[e*4+1], yb = sY[e*4+2], yc = sY[e*4+3];
                const float* fb = &g_feat[sSrc[e] * 320 + 128 + lane * 6];
                float2 f0 = *(const float2*)fb;
                float2 f1 = *(const float2*)(fb + 2);
                float2 f2 = *(const float2*)(fb + 4);
                float w2x = h ? hi20 : lo20, w2y = h ? hi21 : lo21;
                float w3x = h ? hi30 : lo30, w3y = h ? hi31 : lo31;
                q2[0] += w2x*f0.x*y0; q2[1] += w2x*f0.y*y0; q2[2] += w2x*f1.x*y0;
                q2[3] += w2y*f1.y*y0; q2[4] += w2y*f2.x*y0; q2[5] += w2y*f2.y*y0;
                float d0 = f0.x*ya + f0.y*yb + f1.x*yc;
                float d1 = f1.y*ya + f2.x*yb + f2.y*yc;
                q3[0] += w3x*d0; q3[1] += w3y*d1;
            }
        }
        float* bp = &g_agg[cur * 768 + 576 + lane * 6];
        red2(bp,     q2[0], q2[1]);
        red2(bp + 2, q2[2], q2[3]);
        red2(bp + 4, q2[4], q2[5]);
        red2(&g_agg[cur * 768 + 128 + lane * 2], q3[0] * k3, q3[1] * k3);
    }
}

// ---------------------------------------------------------------------------
// Kernel D (R12-proven, full weight stage): output transforms.
// ---------------------------------------------------------------------------
__global__ void __launch_bounds__(256) node_out_kernel(
    const float* __restrict__ Wo0, const float* __restrict__ Wo1,
    float* __restrict__ out)
{
    extern __shared__ float sm[];
    float* zT = sm;              // 192 x 34
    float* sW = sm + 192 * 34;   // 192 x 64
    const int tid = threadIdx.x;
    const int nb  = blockIdx.x * 32;
    const int n0 = (tid >> 5) * 4;
    const int u0 = (tid & 31) * 2;
    const float cs    = 0.9238795325112867f;
    const float kconv = 0.38268343236508984f * 0.25f * 0.07216878364870323f;

    for (int idx = tid; idx < 32 * 192; idx += 256) {
        int n = idx / 192, k = idx % 192;
        zT[k * 34 + n] = (nb + n < N_NODES) ? g_agg[(nb + n) * 768 + k] : 0.f;
    }
    for (int uc = 0; uc < 128; uc += 64) {
        __syncthreads();
        for (int idx = tid; idx < 192 * 64; idx += 256) {
            int k = idx >> 6, u = idx & 63;
            sW[idx] = Wo0[k * 128 + uc + u];
        }
        __syncthreads();
        u64 acc[2][2] = {};
        #pragma unroll 4
        for (int k = 0; k < 192; ++k) {
            u64 a01 = *(const u64*)&zT[k * 34 + n0];
            u64 a23 = *(const u64*)&zT[k * 34 + n0 + 2];
            float2 b = *(const float2*)&sW[k * 64 + u0];
            u64 b0 = dupf(b.x), b1 = dupf(b.y);
            FFMA2(acc[0][0], a01, b0, acc[0][0]); FFMA2(acc[0][1], a01, b1, acc[0][1]);
            FFMA2(acc[1][0], a23, b0, acc[1][0]); FFMA2(acc[1][1], a23, b1, acc[1][1]);
        }
        #pragma unroll
        for (int p = 0; p < 2; ++p) {
            float lo[2], hi[2];
            unpack2(acc[p][0], lo[0], hi[0]);
            unpack2(acc[p][1], lo[1], hi[1]);
            int na = nb + n0 + 2 * p, nc = na + 1;
            if (na < N_NODES) {
                const float* sf = &g_self[na * 320 + uc + u0];
                *(float2*)&out[na * 320 + uc + u0] =
                    make_float2(cs*sf[0] + kconv*lo[0], cs*sf[1] + kconv*lo[1]);
            }
            if (nc < N_NODES) {
                const float* sf = &g_self[nc * 320 + uc + u0];
                *(float2*)&out[nc * 320 + uc + u0] =
                    make_float2(cs*sf[0] + kconv*hi[0], cs*sf[1] + kconv*hi[1]);
            }
        }
    }

    __syncthreads();
    for (int idx = tid; idx < 192 * 64; idx += 256) sW[idx] = Wo1[idx];
    for (int i = 0; i < 3; ++i) {
        __syncthreads();
        for (int idx = tid; idx < 32 * 192; idx += 256) {
            int n = idx / 192, k = idx % 192;
            zT[k * 34 + n] = (nb + n < N_NODES) ? g_agg[(nb + n) * 768 + 192 + k * 3 + i] : 0.f;
        }
        __syncthreads();
        u64 acc[2][2] = {};
        #pragma unroll 4
        for (int k = 0; k < 192; ++k) {
            u64 a01 = *(const u64*)&zT[k * 34 + n0];
            u64 a23 = *(const u64*)&zT[k * 34 + n0 + 2];
            float2 b = *(const float2*)&sW[k * 64 + u0];
            u64 b0 = dupf(b.x), b1 = dupf(b.y);
            FFMA2(acc[0][0], a01, b0, acc[0][0]); FFMA2(acc[0][1], a01, b1, acc[0][1]);
            FFMA2(acc[1][0], a23, b0, acc[1][0]); FFMA2(acc[1][1], a23, b1, acc[1][1]);
        }
        #pragma unroll
        for (int p = 0; p < 2; ++p) {
            float lo[2], hi[2];
            unpack2(acc[p][0], lo[0], hi[0]);
            unpack2(acc[p][1], lo[1], hi[1]);
            int na = nb + n0 + 2 * p, nc = na + 1;
            #pragma unroll
            for (int j = 0; j < 2; ++j) {
                if (na < N_NODES)
                    out[na * 320 + 128 + (u0 + j) * 3 + i] =
                        cs * g_self[na * 320 + 128 + (u0 + j) * 3 + i] + kconv * lo[j];
                if (nc < N_NODES)
                    out[nc * 320 + 128 + (u0 + j) * 3 + i] =
                        cs * g_self[nc * 320 + 128 + (u0 + j) * 3 + i] + kconv * hi[j];
            }
        }
    }
}

// ---------------------------------------------------------------------------
extern "C" void kernel_launch(void* const* d_in, const int* in_sizes, int n_in,
                              void* d_out, int out_size)
{
    const float* node = (const float*)d_in[0];
    const float* edge_attr = (const float*)d_in[1];
    const float* esa  = (const float*)d_in[2];
    const float* Wa0  = (const float*)d_in[3];
    const float* Wa1  = (const float*)d_in[4];
    const float* Wb0  = (const float*)d_in[5];
    const float* Wb1  = (const float*)d_in[6];
    const float* M1   = (const float*)d_in[7];
    const float* M2   = (const float*)d_in[8];
    const float* Wtp0 = (const float*)d_in[9];
    const float* Wtp1 = (const float*)d_in[10];
    const float* Wtp2 = (const float*)d_in[11];
    const float* Wtp3 = (const float*)d_in[12];
    const float* Wo0  = (const float*)d_in[13];
    const float* Wo1  = (const float*)d_in[14];
    const int* esrc   = (const int*)d_in[15];
    const int* edst   = (const int*)d_in[16];
    float* out = (float*)d_out;

    const int smemA = (320 * 34 + 64 * 128) * 4;                           // 76288
    const int smemB = (512 + 4096 + 4096) * 4 + 64 * 4 * 2 + 64 * 4 * 4;   // 36352
    const int smemD = (192 * 34 + 192 * 64) * 4;                           // 75264

    cudaFuncSetAttribute(node_pre_kernel, cudaFuncAttributeMaxDynamicSharedMemorySize, smemA);
    cudaFuncSetAttribute(edge_kernel,     cudaFuncAttributeMaxDynamicSharedMemorySize, smemB);
    cudaFuncSetAttribute(node_out_kernel, cudaFuncAttributeMaxDynamicSharedMemorySize, smemD);

    void *aggp = nullptr, *cntp = nullptr;
    cudaGetSymbolAddress(&aggp, g_agg);
    cudaGetSymbolAddress(&cntp, g_cnt);
    cudaMemsetAsync(aggp, 0, sizeof(float) * (size_t)N_NODES * AGG_DIM);
    cudaMemsetAsync(cntp, 0, sizeof(int) * N_NODES);

    hist_kernel<<<(N_EDGES + 255) / 256, 256>>>(edst);
    scan_kernel<<<1, 1024>>>();
    scatter_kernel<<<(N_EDGES + 255) / 256, 256>>>(edst);

    node_pre_kernel<<<(N_NODES + 31) / 32, 256, smemA>>>(node, Wa0, Wa1, Wb0, Wb1);
    edge_kernel<<<N_EDGES / 64, 256, smemB>>>(edge_attr, esa, M1, M2,
                                              Wtp0, Wtp1, Wtp2, Wtp3, esrc, edst);
    node_out_kernel<<<(N_NODES + 31) / 32, 256, smemD>>>(Wo0, Wo1, out);
}

// round 17
// speedup vs baseline: 1.1819x; 1.0030x over previous
#include <cuda_runtime.h>
#include <math.h>

#define N_NODES 10000
#define N_EDGES 160000
#define FEAT_DIM 320
#define AGG_DIM 768

typedef unsigned long long u64;

__device__ float g_feat[N_NODES * FEAT_DIM];
__device__ float g_self[N_NODES * FEAT_DIM];
__device__ float g_agg [N_NODES * AGG_DIM];
// counting-sort scratch
__device__ int g_cnt [N_NODES];
__device__ int g_off [N_NODES];   // exclusive prefix; consumed (destructively) by scatter
__device__ int g_perm[N_EDGES];

__device__ __forceinline__ float gelu_tanh(float x) {
    float x3 = x * x * x;
    float z  = 0.7978845608028654f * (x + 0.044715f * x3);
    float t;
    asm("tanh.approx.f32 %0, %1;" : "=f"(t) : "f"(z));
    return 0.5f * x * (1.0f + t);
}

__device__ __forceinline__ void red4(float* p, float4 v) {
    asm volatile("red.global.add.v4.f32 [%0], {%1,%2,%3,%4};"
                 :: "l"(p), "f"(v.x), "f"(v.y), "f"(v.z), "f"(v.w) : "memory");
}
__device__ __forceinline__ void red2(float* p, float a, float b) {
    asm volatile("red.global.add.v2.f32 [%0], {%1,%2};"
                 :: "l"(p), "f"(a), "f"(b) : "memory");
}

__device__ __forceinline__ u64 dupf(float x) {
    u64 r; asm("mov.b64 %0, {%1, %1};" : "=l"(r) : "f"(x)); return r;
}
__device__ __forceinline__ void unpack2(u64 v, float& lo, float& hi) {
    asm("mov.b64 {%0, %1}, %2;" : "=f"(lo), "=f"(hi) : "l"(v));
}
#define FFMA2(d, a, b, c) asm("fma.rn.f32x2 %0, %1, %2, %3;" : "=l"(d) : "l"(a), "l"(b), "l"(c))

// ---------------------------------------------------------------------------
// Counting sort of edges by dst (g_off doubles as the fill cursor).
// hist_kernel also zeroes g_agg (overlaps STG-bandwidth zeroing with the
// histogram's L2-atomic traffic; removes a serial 30MB memset node).
// ---------------------------------------------------------------------------
__global__ void hist_kernel(const int* __restrict__ edst) {
    int t = blockIdx.x * 256 + threadIdx.x;
    if (t < N_EDGES) atomicAdd(&g_cnt[edst[t]], 1);
    // grid-stride float4 zero of g_agg (7.68M floats / 1.92M float4)
    const int total4 = N_NODES * AGG_DIM / 4;
    const int nthr   = ((N_EDGES + 255) / 256) * 256;
    float4 z = make_float4(0.f, 0.f, 0.f, 0.f);
    for (int i = t; i < total4; i += nthr)
        ((float4*)g_agg)[i] = z;
}

__global__ void __launch_bounds__(1024) scan_kernel() {
    __shared__ int part[1024];
    const int t = threadIdx.x;
    const int base = t * 10;
    int local[10];
    int s = 0;
    #pragma unroll
    for (int j = 0; j < 10; ++j) {
        int idx = base + j;
        int c = (idx < N_NODES) ? g_cnt[idx] : 0;
        local[j] = s; s += c;
    }
    part[t] = s;
    __syncthreads();
    for (int off = 1; off < 1024; off <<= 1) {
        int v = (t >= off) ? part[t - off] : 0;
        __syncthreads();
        part[t] += v;
        __syncthreads();
    }
    int pre = (t == 0) ? 0 : part[t - 1];
    #pragma unroll
    for (int j = 0; j < 10; ++j) {
        int idx = base + j;
        if (idx < N_NODES) g_off[idx] = pre + local[j];
    }
}

__global__ void scatter_kernel(const int* __restrict__ edst) {
    int e = blockIdx.x * 256 + threadIdx.x;
    if (e < N_EDGES) {
        int pos = atomicAdd(&g_off[edst[e]], 1);   // destructive: g_off is the cursor
        g_perm[pos] = e;
    }
}

// ---------------------------------------------------------------------------
// Kernel A (R12-proven): 32 nodes/block, 256 threads. Weights staged in
// k-chunks of 64 (sW 32KB) -> total smem 76.3KB -> 3 CTAs/SM.
// ---------------------------------------------------------------------------
__global__ void __launch_bounds__(256) node_pre_kernel(
    const float* __restrict__ node,
    const float* __restrict__ Wa0, const float* __restrict__ Wa1,
    const float* __restrict__ Wb0, const float* __restrict__ Wb1)
{
    extern __shared__ float sm[];
    float* xT = sm;               // 320 x 34  (43520 B)
    float* sW = sm + 320 * 34;    // 64 x 128  (32768 B)
    const int tid = threadIdx.x;
    const int nb  = blockIdx.x * 32;

    for (int idx = tid; idx < 32 * 320; idx += 256) {
        int n = idx / 320, k = idx % 320;
        float v = (nb + n < N_NODES) ? node[(nb + n) * 320 + k] : 0.f;
        xT[k * 34 + n] = v;
    }

    const int n0s = (tid >> 5) * 4;
    const int u0s = (tid & 31) * 4;
    for (int w = 0; w < 2; ++w) {
        const float* W = w ? Wb0 : Wa0;
        float* dst     = w ? g_self : g_feat;
        u64 acc[2][4] = {};
        for (int kc = 0; kc < 2; ++kc) {
            __syncthreads();
            for (int idx = tid; idx < 2048; idx += 256)
                ((float4*)sW)[idx] = ((const float4*)W)[kc * 2048 + idx];
            __syncthreads();
            #pragma unroll 4
            for (int k = 0; k < 64; ++k) {
                int kk = kc * 64 + k;
                u64 a01 = *(const u64*)&xT[kk * 34 + n0s];
                u64 a23 = *(const u64*)&xT[kk * 34 + n0s + 2];
                float4 b = *(const float4*)&sW[k * 128 + u0s];
                u64 b0 = dupf(b.x), b1 = dupf(b.y), b2 = dupf(b.z), b3 = dupf(b.w);
                FFMA2(acc[0][0], a01, b0, acc[0][0]); FFMA2(acc[0][1], a01, b1, acc[0][1]);
                FFMA2(acc[0][2], a01, b2, acc[0][2]); FFMA2(acc[0][3], a01, b3, acc[0][3]);
                FFMA2(acc[1][0], a23, b0, acc[1][0]); FFMA2(acc[1][1], a23, b1, acc[1][1]);
                FFMA2(acc[1][2], a23, b2, acc[1][2]); FFMA2(acc[1][3], a23, b3, acc[1][3]);
            }
        }
        const float sc = 0.08838834764831845f;
        #pragma unroll
        for (int p = 0; p < 2; ++p) {
            float lo[4], hi[4];
            #pragma unroll
            for (int j = 0; j < 4; ++j) unpack2(acc[p][j], lo[j], hi[j]);
            int na = nb + n0s + 2 * p, nc = na + 1;
            if (na < N_NODES)
                *(float4*)&dst[na * 320 + u0s] = make_float4(lo[0]*sc, lo[1]*sc, lo[2]*sc, lo[3]*sc);
            if (nc < N_NODES)
                *(float4*)&dst[nc * 320 + u0s] = make_float4(hi[0]*sc, hi[1]*sc, hi[2]*sc, hi[3]*sc);
        }
    }

    // ---- vector part: Wa1 (half 0) and Wb1 (half 1) concurrently ----
    __syncthreads();
    for (int idx = tid; idx < 1024; idx += 256) ((float4*)sW)[idx] = ((const float4*)Wa1)[idx];
    for (int idx = tid; idx < 1024; idx += 256) ((float4*)(sW + 4096))[idx] = ((const float4*)Wb1)[idx];
    __syncthreads();
    {
        const int half = tid >> 7;
        const int wt   = tid & 127;
        const int n0   = (wt >> 4) * 4;
        const int u0   = (wt & 15) * 4;
        const float* sWh = sW + half * 4096;
        float* dst       = half ? g_self : g_feat;
        for (int i = 0; i < 3; ++i) {
            u64 acc[2][4] = {};
            #pragma unroll 4
            for (int v = 0; v < 64; ++v) {
                int k = 128 + v * 3 + i;
                u64 a01 = *(const u64*)&xT[k * 34 + n0];
                u64 a23 = *(const u64*)&xT[k * 34 + n0 + 2];
                float4 b = *(const float4*)&sWh[v * 64 + u0];
                u64 b0 = dupf(b.x), b1 = dupf(b.y), b2 = dupf(b.z), b3 = dupf(b.w);
                FFMA2(acc[0][0], a01, b0, acc[0][0]); FFMA2(acc[0][1], a01, b1, acc[0][1]);
                FFMA2(acc[0][2], a01, b2, acc[0][2]); FFMA2(acc[0][3], a01, b3, acc[0][3]);
                FFMA2(acc[1][0], a23, b0, acc[1][0]); FFMA2(acc[1][1], a23, b1, acc[1][1]);
                FFMA2(acc[1][2], a23, b2, acc[1][2]); FFMA2(acc[1][3], a23, b3, acc[1][3]);
            }
            const float sc = 0.125f;
            #pragma unroll
            for (int p = 0; p < 2; ++p) {
                float lo[4], hi[4];
                #pragma unroll
                for (int j = 0; j < 4; ++j) unpack2(acc[p][j], lo[j], hi[j]);
                int na = nb + n0 + 2 * p, nc = na + 1;
                #pragma unroll
                for (int j = 0; j < 4; ++j) {
                    if (na < N_NODES) dst[na * 320 + 128 + (u0 + j) * 3 + i] = lo[j] * sc;
                    if (nc < N_NODES) dst[nc * 320 + 128 + (u0 + j) * 3 + i] = hi[j] * sc;
                }
            }
        }
    }
}

// ---------------------------------------------------------------------------
// Kernel B (R16-proven): R8 structure + min 3 CTAs/SM launch bounds.
// ---------------------------------------------------------------------------
__global__ void __launch_bounds__(256, 3) edge_kernel(
    const float* __restrict__ edge_attr, const float* __restrict__ esa,
    const float* __restrict__ M1, const float* __restrict__ M2,
    const float* __restrict__ Wtp0, const float* __restrict__ Wtp1,
    const float* __restrict__ Wtp2, const float* __restrict__ Wtp3,
    const int* __restrict__ esrc, const int* __restrict__ edst)
{
    extern __shared__ float sm[];
    float* sInT = sm;             // 8 x 64
    float* sH1T = sm + 512;       // 64 x 64  [chan][edge]
    float* sH2T = sH1T + 4096;    // 64 x 64  [chan][edge]
    int*   sSrc = (int*)(sH2T + 4096);
    int*   sDst = sSrc + 64;
    float* sY   = (float*)(sDst + 64);

    const int tid = threadIdx.x;
    const int eb  = blockIdx.x * 64;

    for (int idx = tid; idx < 512; idx += 256) {
        int el = idx >> 3, k = idx & 7;
        int e = __ldg(&g_perm[eb + el]);
        sInT[k * 64 + el] = esa[e * 8 + k];
    }
    if (tid < 64) {
        int e = __ldg(&g_perm[eb + tid]);
        sSrc[tid] = esrc[e];
        sDst[tid] = edst[e];
        float4 y = *(const float4*)&edge_attr[e * 4];
        sY[tid * 4 + 0] = y.x; sY[tid * 4 + 1] = y.y;
        sY[tid * 4 + 2] = y.z; sY[tid * 4 + 3] = y.w;
    }
    __syncthreads();

    // h1 = gelu((esa @ M1)/sqrt(8))
    for (int idx = tid; idx < 4096; idx += 256) {
        int u = idx >> 6, el = idx & 63;
        float s = 0.f;
        #pragma unroll
        for (int k = 0; k < 8; ++k) s += sInT[k * 64 + el] * __ldg(&M1[k * 64 + u]);
        sH1T[idx] = gelu_tanh(s * 0.3535533905932738f);
    }
    __syncthreads();

    // h2 = gelu((h1 @ M2)/sqrt(64)), M2 straight from gmem
    {
        const int e0 = (tid & 15) * 4, u0 = (tid >> 4) * 4;
        u64 acc[4][2] = {};
        #pragma unroll 4
        for (int k = 0; k < 64; ++k) {
            float4 a = *(const float4*)&sH1T[k * 64 + e0];
            u64 ad0 = dupf(a.x), ad1 = dupf(a.y), ad2 = dupf(a.z), ad3 = dupf(a.w);
            ulonglong2 b = __ldg((const ulonglong2*)&M2[k * 64 + u0]);
            FFMA2(acc[0][0], ad0, b.x, acc[0][0]); FFMA2(acc[0][1], ad0, b.y, acc[0][1]);
            FFMA2(acc[1][0], ad1, b.x, acc[1][0]); FFMA2(acc[1][1], ad1, b.y, acc[1][1]);
            FFMA2(acc[2][0], ad2, b.x, acc[2][0]); FFMA2(acc[2][1], ad2, b.y, acc[2][1]);
            FFMA2(acc[3][0], ad3, b.x, acc[3][0]); FFMA2(acc[3][1], ad3, b.y, acc[3][1]);
        }
        #pragma unroll
        for (int e = 0; e < 4; ++e)
            #pragma unroll
            for (int j = 0; j < 2; ++j) {
                float lo, hi; unpack2(acc[e][j], lo, hi);
                sH2T[(u0 + 2*j    ) * 64 + e0 + e] = gelu_tanh(lo * 0.125f);
                sH2T[(u0 + 2*j + 1) * 64 + e0 + e] = gelu_tanh(hi * 0.125f);
            }
    }
    __syncthreads();

    // ============ barrier-free fused phases ============
    const int wid = tid >> 5, lane = tid & 31;
    const int we0 = wid * 8;

    // ---- p0: w0 -> mid0a (run-accumulated) ----
    {
        u64 acc[4][4] = {};
        #pragma unroll 4
        for (int k = 0; k < 64; ++k) {
            const float* ap = &sH2T[k * 64 + we0];
            ulonglong2 aa0 = *(const ulonglong2*)(ap);
            ulonglong2 aa1 = *(const ulonglong2*)(ap + 4);
            u64 a0 = aa0.x, a1 = aa0.y, a2 = aa1.x, a3 = aa1.y;
            float4 b = __ldg((const float4*)&Wtp0[k * 128 + lane * 4]);
            u64 b0 = dupf(b.x), b1 = dupf(b.y), b2 = dupf(b.z), b3 = dupf(b.w);
            FFMA2(acc[0][0], a0, b0, acc[0][0]); FFMA2(acc[0][1], a0, b1, acc[0][1]);
            FFMA2(acc[0][2], a0, b2, acc[0][2]); FFMA2(acc[0][3], a0, b3, acc[0][3]);
            FFMA2(acc[1][0], a1, b0, acc[1][0]); FFMA2(acc[1][1], a1, b1, acc[1][1]);
            FFMA2(acc[1][2], a1, b2, acc[1][2]); FFMA2(acc[1][3], a1, b3, acc[1][3]);
            FFMA2(acc[2][0], a2, b0, acc[2][0]); FFMA2(acc[2][1], a2, b1, acc[2][1]);
            FFMA2(acc[2][2], a2, b2, acc[2][2]); FFMA2(acc[2][3], a2, b3, acc[2][3]);
            FFMA2(acc[3][0], a3, b0, acc[3][0]); FFMA2(acc[3][1], a3, b1, acc[3][1]);
            FFMA2(acc[3][2], a3, b2, acc[3][2]); FFMA2(acc[3][3], a3, b3, acc[3][3]);
        }
        int cur = sDst[we0];
        float4 av = make_float4(0.f, 0.f, 0.f, 0.f);
        #pragma unroll
        for (int p = 0; p < 4; ++p) {
            float lo[4], hi[4];
            #pragma unroll
            for (int j = 0; j < 4; ++j) unpack2(acc[p][j], lo[j], hi[j]);
            #pragma unroll
            for (int h = 0; h < 2; ++h) {
                int e = we0 + 2 * p + h;
                int dst = sDst[e];
                if (dst != cur) {
                    red4(&g_agg[cur * 768 + lane * 4], av);
                    av = make_float4(0.f, 0.f, 0.f, 0.f);
                    cur = dst;
                }
                float y0 = sY[e * 4] * 0.125f;
                float4 f = *(const float4*)&g_feat[sSrc[e] * 320 + lane * 4];
                float wa = h ? hi[0] : lo[0], wb = h ? hi[1] : lo[1];
                float wc = h ? hi[2] : lo[2], wd = h ? hi[3] : lo[3];
                av.x += wa*f.x*y0; av.y += wb*f.y*y0;
                av.z += wc*f.z*y0; av.w += wd*f.w*y0;
            }
        }
        red4(&g_agg[cur * 768 + lane * 4], av);
    }

    // ---- p1: w1 -> mid1a (run-accumulated) ----
    {
        u64 acc[4][4] = {};
        #pragma unroll 4
        for (int k = 0; k < 64; ++k) {
            const float* ap = &sH2T[k * 64 + we0];
            ulonglong2 aa0 = *(const ulonglong2*)(ap);
            ulonglong2 aa1 = *(const ulonglong2*)(ap + 4);
            u64 a0 = aa0.x, a1 = aa0.y, a2 = aa1.x, a3 = aa1.y;
            float4 b = __ldg((const float4*)&Wtp1[k * 128 + lane * 4]);
            u64 b0 = dupf(b.x), b1 = dupf(b.y), b2 = dupf(b.z), b3 = dupf(b.w);
            FFMA2(acc[0][0], a0, b0, acc[0][0]); FFMA2(acc[0][1], a0, b1, acc[0][1]);
            FFMA2(acc[0][2], a0, b2, acc[0][2]); FFMA2(acc[0][3], a0, b3, acc[0][3]);
            FFMA2(acc[1][0], a1, b0, acc[1][0]); FFMA2(acc[1][1], a1, b1, acc[1][1]);
            FFMA2(acc[1][2], a1, b2, acc[1][2]); FFMA2(acc[1][3], a1, b3, acc[1][3]);
            FFMA2(acc[2][0], a2, b0, acc[2][0]); FFMA2(acc[2][1], a2, b1, acc[2][1]);
            FFMA2(acc[2][2], a2, b2, acc[2][2]); FFMA2(acc[2][3], a2, b3, acc[2][3]);
            FFMA2(acc[3][0], a3, b0, acc[3][0]); FFMA2(acc[3][1], a3, b1, acc[3][1]);
            FFMA2(acc[3][2], a3, b2, acc[3][2]); FFMA2(acc[3][3], a3, b3, acc[3][3]);
        }
        int cur = sDst[we0];
        float a[12];
        #pragma unroll
        for (int j = 0; j < 12; ++j) a[j] = 0.f;
        #pragma unroll
        for (int p = 0; p < 4; ++p) {
            float lo[4], hi[4];
            #pragma unroll
            for (int j = 0; j < 4; ++j) unpack2(acc[p][j], lo[j], hi[j]);
            #pragma unroll
            for (int h = 0; h < 2; ++h) {
                int e = we0 + 2 * p + h;
                int dst = sDst[e];
                if (dst != cur) {
                    float* bp = &g_agg[cur * 768 + 192 + lane * 12];
                    red4(bp,     make_float4(a[0], a[1], a[2],  a[3]));
                    red4(bp + 4, make_float4(a[4], a[5], a[6],  a[7]));
                    red4(bp + 8, make_float4(a[8], a[9], a[10], a[11]));
                    #pragma unroll
                    for (int j = 0; j < 12; ++j) a[j] = 0.f;
                    cur = dst;
                }
                float ya = sY[e*4+1] * 0.125f, yb = sY[e*4+2] * 0.125f, yc = sY[e*4+3] * 0.125f;
                float4 f = *(const float4*)&g_feat[sSrc[e] * 320 + lane * 4];
                float wa = h ? hi[0] : lo[0], wb = h ? hi[1] : lo[1];
                float wc = h ? hi[2] : lo[2], wd = h ? hi[3] : lo[3];
                float t0 = wa*f.x, t1 = wb*f.y, t2 = wc*f.z, t3 = wd*f.w;
                a[0] += t0*ya; a[1]  += t0*yb; a[2]  += t0*yc;
                a[3] += t1*ya; a[4]  += t1*yb; a[5]  += t1*yc;
                a[6] += t2*ya; a[7]  += t2*yb; a[8]  += t2*yc;
                a[9] += t3*ya; a[10] += t3*yb; a[11] += t3*yc;
            }
        }
        float* bp = &g_agg[cur * 768 + 192 + lane * 12];
        red4(bp,     make_float4(a[0], a[1], a[2],  a[3]));
        red4(bp + 4, make_float4(a[4], a[5], a[6],  a[7]));
        red4(bp + 8, make_float4(a[8], a[9], a[10], a[11]));
    }

    // ---- p2+p3: w2 -> mid1b, w3 -> mid0b (run-accumulated) ----
    {
        u64 ac2[4][2] = {}, ac3[4][2] = {};
        #pragma unroll 4
        for (int k = 0; k < 64; ++k) {
            const float* ap = &sH2T[k * 64 + we0];
            ulonglong2 aa0 = *(const ulonglong2*)(ap);
            ulonglong2 aa1 = *(const ulonglong2*)(ap + 4);
            u64 a0 = aa0.x, a1 = aa0.y, a2 = aa1.x, a3 = aa1.y;
            float2 b2v = __ldg((const float2*)&Wtp2[k * 64 + lane * 2]);
            float2 b3v = __ldg((const float2*)&Wtp3[k * 64 + lane * 2]);
            u64 b20 = dupf(b2v.x), b21 = dupf(b2v.y);
            u64 b30 = dupf(b3v.x), b31 = dupf(b3v.y);
            FFMA2(ac2[0][0], a0, b20, ac2[0][0]); FFMA2(ac2[0][1], a0, b21, ac2[0][1]);
            FFMA2(ac2[1][0], a1, b20, ac2[1][0]); FFMA2(ac2[1][1], a1, b21, ac2[1][1]);
            FFMA2(ac2[2][0], a2, b20, ac2[2][0]); FFMA2(ac2[2][1], a2, b21, ac2[2][1]);
            FFMA2(ac2[3][0], a3, b20, ac2[3][0]); FFMA2(ac2[3][1], a3, b21, ac2[3][1]);
            FFMA2(ac3[0][0], a0, b30, ac3[0][0]); FFMA2(ac3[0][1], a0, b31, ac3[0][1]);
            FFMA2(ac3[1][0], a1, b30, ac3[1][0]); FFMA2(ac3[1][1], a1, b31, ac3[1][1]);
            FFMA2(ac3[2][0], a2, b30, ac3[2][0]); FFMA2(ac3[2][1], a2, b31, ac3[2][1]);
            FFMA2(ac3[3][0], a3, b30, ac3[3][0]); FFMA2(ac3[3][1], a3, b31, ac3[3][1]);
        }
        const float k3 = 0.125f * 0.5773502691896258f;
        int cur = sDst[we0];
        float q2[6] = {0.f, 0.f, 0.f, 0.f, 0.f, 0.f};
        float q3[2] = {0.f, 0.f};
        #pragma unroll
        for (int p = 0; p < 4; ++p) {
            float lo20, hi20, lo21, hi21, lo30, hi30, lo31, hi31;
            unpack2(ac2[p][0], lo20, hi20); unpack2(ac2[p][1], lo21, hi21);
            unpack2(ac3[p][0], lo30, hi30); unpack2(ac3[p][1], lo31, hi31);
            #pragma unroll
            for (int h = 0; h < 2; ++h) {
                int e = we0 + 2 * p + h;
                int dst = sDst[e];
                if (dst != cur) {
                    float* bp = &g_agg[cur * 768 + 576 + lane * 6];
                    red2(bp,     q2[0], q2[1]);
                    red2(bp + 2, q2[2], q2[3]);
                    red2(bp + 4, q2[4], q2[5]);
                    red2(&g_agg[cur * 768 + 128 + lane * 2], q3[0] * k3, q3[1] * k3);
                    #pragma unroll
                    for (int j = 0; j < 6; ++j) q2[j] = 0.f;
                    q3[0] = 0.f; q3[1] = 0.f;
                    cur = dst;
                }
                float y0 = sY[e*4] * 0.125f;
                float ya = sY[e*4+1], yb = sY[e*4+2], yc = sY[e*4+3];
                const float* fb = &g_feat[sSrc[e] * 320 + 128 + lane * 6];
                float2 f0 = *(const float2*)fb;
                float2 f1 = *(const float2*)(fb + 2);
                float2 f2 = *(const float2*)(fb + 4);
                float w2x = h ? hi20 : lo20, w2y = h ? hi21 : lo21;
                float w3x = h ? hi30 : lo30, w3y = h ? hi31 : lo31;
                q2[0] += w2x*f0.x*y0; q2[1] += w2x*f0.y*y0; q2[2] += w2x*f1.x*y0;
                q2[3] += w2y*f1.y*y0; q2[4] += w2y*f2.x*y0; q2[5] += w2y*f2.y*y0;
                float d0 = f0.x*ya + f0.y*yb + f1.x*yc;
                float d1 = f1.y*ya + f2.x*yb + f2.y*yc;
                q3[0] += w3x*d0; q3[1] += w3y*d1;
            }
        }
        float* bp = &g_agg[cur * 768 + 576 + lane * 6];
        red2(bp,     q2[0], q2[1]);
        red2(bp + 2, q2[2], q2[3]);
        red2(bp + 4, q2[4], q2[5]);
        red2(&g_agg[cur * 768 + 128 + lane * 2], q3[0] * k3, q3[1] * k3);
    }
}

// ---------------------------------------------------------------------------
// Kernel D (R12-proven, full weight stage): output transforms.
// ---------------------------------------------------------------------------
__global__ void __launch_bounds__(256) node_out_kernel(
    const float* __restrict__ Wo0, const float* __restrict__ Wo1,
    float* __restrict__ out)
{
    extern __shared__ float sm[];
    float* zT = sm;              // 192 x 34
    float* sW = sm + 192 * 34;   // 192 x 64
    const int tid = threadIdx.x;
    const int nb  = blockIdx.x * 32;
    const int n0 = (tid >> 5) * 4;
    const int u0 = (tid & 31) * 2;
    const float cs    = 0.9238795325112867f;
    const float kconv = 0.38268343236508984f * 0.25f * 0.07216878364870323f;

    for (int idx = tid; idx < 32 * 192; idx += 256) {
        int n = idx / 192, k = idx % 192;
        zT[k * 34 + n] = (nb + n < N_NODES) ? g_agg[(nb + n) * 768 + k] : 0.f;
    }
    for (int uc = 0; uc < 128; uc += 64) {
        __syncthreads();
        for (int idx = tid; idx < 192 * 64; idx += 256) {
            int k = idx >> 6, u = idx & 63;
            sW[idx] = Wo0[k * 128 + uc + u];
        }
        __syncthreads();
        u64 acc[2][2] = {};
        #pragma unroll 4
        for (int k = 0; k < 192; ++k) {
            u64 a01 = *(const u64*)&zT[k * 34 + n0];
            u64 a23 = *(const u64*)&zT[k * 34 + n0 + 2];
            float2 b = *(const float2*)&sW[k * 64 + u0];
            u64 b0 = dupf(b.x), b1 = dupf(b.y);
            FFMA2(acc[0][0], a01, b0, acc[0][0]); FFMA2(acc[0][1], a01, b1, acc[0][1]);
            FFMA2(acc[1][0], a23, b0, acc[1][0]); FFMA2(acc[1][1], a23, b1, acc[1][1]);
        }
        #pragma unroll
        for (int p = 0; p < 2; ++p) {
            float lo[2], hi[2];
            unpack2(acc[p][0], lo[0], hi[0]);
            unpack2(acc[p][1], lo[1], hi[1]);
            int na = nb + n0 + 2 * p, nc = na + 1;
            if (na < N_NODES) {
                const float* sf = &g_self[na * 320 + uc + u0];
                *(float2*)&out[na * 320 + uc + u0] =
                    make_float2(cs*sf[0] + kconv*lo[0], cs*sf[1] + kconv*lo[1]);
            }
            if (nc < N_NODES) {
                const float* sf = &g_self[nc * 320 + uc + u0];
                *(float2*)&out[nc * 320 + uc + u0] =
                    make_float2(cs*sf[0] + kconv*hi[0], cs*sf[1] + kconv*hi[1]);
            }
        }
    }

    __syncthreads();
    for (int idx = tid; idx < 192 * 64; idx += 256) sW[idx] = Wo1[idx];
    for (int i = 0; i < 3; ++i) {
        __syncthreads();
        for (int idx = tid; idx < 32 * 192; idx += 256) {
            int n = idx / 192, k = idx % 192;
            zT[k * 34 + n] = (nb + n < N_NODES) ? g_agg[(nb + n) * 768 + 192 + k * 3 + i] : 0.f;
        }
        __syncthreads();
        u64 acc[2][2] = {};
        #pragma unroll 4
        for (int k = 0; k < 192; ++k) {
            u64 a01 = *(const u64*)&zT[k * 34 + n0];
            u64 a23 = *(const u64*)&zT[k * 34 + n0 + 2];
            float2 b = *(const float2*)&sW[k * 64 + u0];
            u64 b0 = dupf(b.x), b1 = dupf(b.y);
            FFMA2(acc[0][0], a01, b0, acc[0][0]); FFMA2(acc[0][1], a01, b1, acc[0][1]);
            FFMA2(acc[1][0], a23, b0, acc[1][0]); FFMA2(acc[1][1], a23, b1, acc[1][1]);
        }
        #pragma unroll
        for (int p = 0; p < 2; ++p) {
            float lo[2], hi[2];
            unpack2(acc[p][0], lo[0], hi[0]);
            unpack2(acc[p][1], lo[1], hi[1]);
            int na = nb + n0 + 2 * p, nc = na + 1;
            #pragma unroll
            for (int j = 0; j < 2; ++j) {
                if (na < N_NODES)
                    out[na * 320 + 128 + (u0 + j) * 3 + i] =
                        cs * g_self[na * 320 + 128 + (u0 + j) * 3 + i] + kconv * lo[j];
                if (nc < N_NODES)
                    out[nc * 320 + 128 + (u0 + j) * 3 + i] =
                        cs * g_self[nc * 320 + 128 + (u0 + j) * 3 + i] + kconv * hi[j];
            }
        }
    }
}

// ---------------------------------------------------------------------------
extern "C" void kernel_launch(void* const* d_in, const int* in_sizes, int n_in,
                              void* d_out, int out_size)
{
    const float* node = (const float*)d_in[0];
    const float* edge_attr = (const float*)d_in[1];
    const float* esa  = (const float*)d_in[2];
    const float* Wa0  = (const float*)d_in[3];
    const float* Wa1  = (const float*)d_in[4];
    const float* Wb0  = (const float*)d_in[5];
    const float* Wb1  = (const float*)d_in[6];
    const float* M1   = (const float*)d_in[7];
    const float* M2   = (const float*)d_in[8];
    const float* Wtp0 = (const float*)d_in[9];
    const float* Wtp1 = (const float*)d_in[10];
    const float* Wtp2 = (const float*)d_in[11];
    const float* Wtp3 = (const float*)d_in[12];
    const float* Wo0  = (const float*)d_in[13];
    const float* Wo1  = (const float*)d_in[14];
    const int* esrc   = (const int*)d_in[15];
    const int* edst   = (const int*)d_in[16];
    float* out = (float*)d_out;

    const int smemA = (320 * 34 + 64 * 128) * 4;                           // 76288
    const int smemB = (512 + 4096 + 4096) * 4 + 64 * 4 * 2 + 64 * 4 * 4;   // 36352
    const int smemD = (192 * 34 + 192 * 64) * 4;                           // 75264

    cudaFuncSetAttribute(node_pre_kernel, cudaFuncAttributeMaxDynamicSharedMemorySize, smemA);
    cudaFuncSetAttribute(edge_kernel,     cudaFuncAttributeMaxDynamicSharedMemorySize, smemB);
    cudaFuncSetAttribute(node_out_kernel, cudaFuncAttributeMaxDynamicSharedMemorySize, smemD);

    void* cntp = nullptr;
    cudaGetSymbolAddress(&cntp, g_cnt);
    cudaMemsetAsync(cntp, 0, sizeof(int) * N_NODES);

    hist_kernel<<<(N_EDGES + 255) / 256, 256>>>(edst);   // also zeroes g_agg
    scan_kernel<<<1, 1024>>>();
    scatter_kernel<<<(N_EDGES + 255) / 256, 256>>>(edst);

    node_pre_kernel<<<(N_NODES + 31) / 32, 256, smemA>>>(node, Wa0, Wa1, Wb0, Wb1);
    edge_kernel<<<N_EDGES / 64, 256, smemB>>>(edge_attr, esa, M1, M2,
                                              Wtp0, Wtp1, Wtp2, Wtp3, esrc, edst);
    node_out_kernel<<<(N_NODES + 31) / 32, 256, smemD>>>(Wo0, Wo1, out);
}